// round 1
// baseline (speedup 1.0000x reference)
#include <cuda_runtime.h>

#define NU   128
#define MS   64
#define INC  323          // inputs row: [0:128) interact | [128:192) corr | [192:320) topic | 320 t | 321 a | 322 h
#define BMAX 4096

// ---------------- scratch (device globals; no allocation) ----------------
__device__ float g_hpt   [BMAX*NU];      // h_pre_tilde
__device__ float g_gain  [3*BMAX*NU];    // time/attempt/hint gate outputs
__device__ float g_lg    [BMAX*NU];      // learning_gain
__device__ float g_c     [BMAX*NU];      // per-batch gate3 constant
__device__ float g_htilde[BMAX*NU];
__device__ float g_preds [BMAX];
__device__ float g_ws    [3*NU];         // colsums of gate3_W factor blocks

__device__ __forceinline__ float sigmoidf(float x){ return 1.f/(1.f+__expf(-x)); }

// ---------------- K0: colsums of gate3_W rows 256..405 ----------------
__global__ void k0_wsum(const float* __restrict__ g3W){
    int n = threadIdx.x;
    #pragma unroll
    for(int g=0; g<3; g++){
        float s = 0.f;
        for(int u=0; u<50; u++) s += g3W[(256 + g*50 + u)*NU + n];
        g_ws[g*NU + n] = s;
    }
}

// ---------------- K1: h_pre_tilde[b,n] = sum_m corr[b,m]*h_pre[b,m,n] ----------------
__global__ __launch_bounds__(128) void k1_hpt(const float* __restrict__ inp,
                                              const float* __restrict__ states){
    int b = blockIdx.x, n = threadIdx.x;
    __shared__ float corr[MS];
    if(n < MS) corr[n] = inp[b*INC + NU + n];
    __syncthreads();
    const float* hp = states + (size_t)b*MS*NU;
    float a0=0.f,a1=0.f,a2=0.f,a3=0.f;
    #pragma unroll
    for(int m=0; m<MS; m+=4){
        a0 = fmaf(corr[m+0], hp[(m+0)*NU + n], a0);
        a1 = fmaf(corr[m+1], hp[(m+1)*NU + n], a1);
        a2 = fmaf(corr[m+2], hp[(m+2)*NU + n], a2);
        a3 = fmaf(corr[m+3], hp[(m+3)*NU + n], a3);
    }
    g_hpt[b*NU + n] = (a0+a1)+(a2+a3);
}

// ---------------- shared-tile GEMM helper: acc[j] += A[row][:] @ W[:,cg*8+j], K=128 ----------------
// Block = 256 threads, 16 rows x 16 col-groups of 8. W streamed global->smem in 32-row tiles.
__device__ __forceinline__ void gemm16(const float A[16][NU], const float* __restrict__ W,
                                       float Ws[32][NU], int row, int cg, float acc[8]){
    #pragma unroll 1
    for(int kt=0; kt<4; kt++){
        __syncthreads();
        const float4* src = (const float4*)(W + kt*32*NU);
        float4* dst = (float4*)&Ws[0][0];
        #pragma unroll
        for(int i=0; i<4; i++) dst[threadIdx.x + i*256] = src[threadIdx.x + i*256];
        __syncthreads();
        #pragma unroll
        for(int k=0; k<32; k++){
            float a = A[row][kt*32 + k];
            float4 w0 = *(const float4*)&Ws[k][cg*8];
            float4 w1 = *(const float4*)&Ws[k][cg*8 + 4];
            acc[0]=fmaf(a,w0.x,acc[0]); acc[1]=fmaf(a,w0.y,acc[1]);
            acc[2]=fmaf(a,w0.z,acc[2]); acc[3]=fmaf(a,w0.w,acc[3]);
            acc[4]=fmaf(a,w1.x,acc[4]); acc[5]=fmaf(a,w1.y,acc[5]);
            acc[6]=fmaf(a,w1.z,acc[6]); acc[7]=fmaf(a,w1.w,acc[7]);
        }
    }
}

// ---------------- K2: preds, three gates, gate3 per-batch constant c ----------------
__global__ __launch_bounds__(256) void k2_vec(const float* __restrict__ inp,
    const float* __restrict__ outW, const float* __restrict__ outb,
    const float* __restrict__ tgW,  const float* __restrict__ tgb,
    const float* __restrict__ agW,  const float* __restrict__ agb,
    const float* __restrict__ hgW,  const float* __restrict__ hgb,
    const float* __restrict__ g3W,  const float* __restrict__ g3b){

    __shared__ float hpt[16][NU], em[16][NU], tp[16][NU], fact[16][3];
    __shared__ __align__(16) float Ws[32][NU];
    int t = threadIdx.x, row = t>>4, cg = t&15;
    int b0 = blockIdx.x*16, b = b0 + row;

    for(int i=t; i<16*NU; i+=256){
        int r = i>>7, c = i&127;
        hpt[r][c] = g_hpt[(b0+r)*NU + c];
        em [r][c] = inp[(b0+r)*INC + c];
        tp [r][c] = inp[(b0+r)*INC + NU + MS + c];
    }
    if(t < 48){ int r=t/3, g=t%3; fact[r][g] = inp[(b0+r)*INC + 320 + g]; }
    __syncthreads();

    float acc[8];
    // preds = mean(sigmoid([hpt|topic]@outW + outb))
    #pragma unroll
    for(int j=0;j<8;j++) acc[j]=0.f;
    gemm16(hpt, outW,        Ws, row, cg, acc);
    gemm16(tp,  outW + NU*NU,Ws, row, cg, acc);
    {
        float s = 0.f;
        #pragma unroll
        for(int j=0;j<8;j++) s += sigmoidf(acc[j] + outb[cg*8+j]);
        for(int o=8;o>0;o>>=1) s += __shfl_xor_sync(0xffffffffu, s, o, 16);
        if(cg==0) g_preds[b] = s * (1.f/NU);
    }
    // gates
    const float* Wg3[3] = {tgW, agW, hgW};
    const float* bg3[3] = {tgb, agb, hgb};
    #pragma unroll 1
    for(int g=0; g<3; g++){
        #pragma unroll
        for(int j=0;j<8;j++) acc[j]=0.f;
        gemm16(hpt, Wg3[g],         Ws, row, cg, acc);
        gemm16(em,  Wg3[g] + NU*NU, Ws, row, cg, acc);
        float f = fact[row][g];
        float gain = 0.3f + 0.7f*sigmoidf(10.f*(f - 0.3f));
        #pragma unroll
        for(int j=0;j<8;j++){
            int n = cg*8 + j;
            g_gain[(size_t)g*BMAX*NU + b*NU + n] = sigmoidf((acc[j] + bg3[g][n]) * gain);
        }
    }
    // c[b,n] = interact @ g3W[128:256] + t*ws0 + a*ws1 + h*ws2 + g3b
    #pragma unroll
    for(int j=0;j<8;j++) acc[j]=0.f;
    gemm16(em, g3W + NU*NU, Ws, row, cg, acc);
    #pragma unroll
    for(int j=0;j<8;j++){
        int n = cg*8 + j;
        g_c[b*NU + n] = acc[j] + fact[row][0]*g_ws[n] + fact[row][1]*g_ws[NU+n]
                               + fact[row][2]*g_ws[2*NU+n] + g3b[n];
    }
}

// ---------------- K3: fusion -> learning_gain ----------------
__global__ __launch_bounds__(256) void k3_fusion(const float* __restrict__ tw,
    const float* __restrict__ aw, const float* __restrict__ hw,
    const float* __restrict__ Wf, const float* __restrict__ bias){

    __shared__ float ga[3][16][NU];
    __shared__ __align__(16) float Ws[32][NU];
    __shared__ float Wf_s[4];
    int t = threadIdx.x, row = t>>4, cg = t&15;
    int b0 = blockIdx.x*16, b = b0 + row;

    for(int i=t; i<3*16*NU; i+=256){
        int g = i/(16*NU), r = (i>>7)&15, c = i&127;
        ga[g][r][c] = g_gain[(size_t)g*BMAX*NU + (b0+r)*NU + c];
    }
    if(t<4) Wf_s[t] = Wf[t];
    __syncthreads();

    const float* Wg3[3] = {tw, aw, hw};
    float fus[8];
    #pragma unroll
    for(int j=0;j<8;j++) fus[j]=0.f;

    #pragma unroll 1
    for(int r=0; r<4; r++){
        float prod[8];
        #pragma unroll 1
        for(int g=0; g<3; g++){
            float dot[8];
            #pragma unroll
            for(int j=0;j<8;j++) dot[j]=0.f;
            gemm16(ga[g], Wg3[g] + (size_t)r*129*NU, Ws, row, cg, dot);
            #pragma unroll
            for(int j=0;j<8;j++) dot[j] += Wg3[g][((size_t)r*129 + 128)*NU + cg*8 + j]; // pad row
            if(g==0){ for(int j=0;j<8;j++) prod[j]=dot[j]; }
            else    { for(int j=0;j<8;j++) prod[j]*=dot[j]; }
        }
        #pragma unroll
        for(int j=0;j<8;j++) fus[j] = fmaf(Wf_s[r], prod[j], fus[j]);
    }
    #pragma unroll
    for(int j=0;j<8;j++){
        int n = cg*8 + j;
        g_lg[b*NU + n] = fmaxf(fus[j] + bias[n], 0.f);
    }
}

// ---------------- K4: forget gate GEMM + state update + h_tilde ----------------
// per-block: one batch. SMEM: W1(128x128) | h_pre(64x128) | c | lg | corr | ht partials
__global__ __launch_bounds__(256) void k4_main(const float* __restrict__ inp,
                                               const float* __restrict__ states,
                                               const float* __restrict__ g3W,
                                               float* __restrict__ out){
    extern __shared__ float sm[];
    float (*Ws)[NU]  = (float(*)[NU])sm;                        // 16384
    float (*A)[NU]   = (float(*)[NU])(sm + NU*NU);              // 8192
    float* c_s       = sm + NU*NU + MS*NU;                      // 128
    float* lg_s      = c_s + NU;                                // 128
    float* corr_s    = lg_s + NU;                               // 64
    float (*htr)[NU] = (float(*)[NU])(corr_s + MS);             // 8*128

    int b = blockIdx.x, t = threadIdx.x;
    {
        const float4* ws = (const float4*)g3W;                  // rows 0..127 (h_pre block)
        float4* wd = (float4*)sm;
        for(int i=t; i<NU*NU/4; i+=256) wd[i] = ws[i];
        const float4* as = (const float4*)(states + (size_t)b*MS*NU);
        float4* ad = (float4*)A;
        for(int i=t; i<MS*NU/4; i+=256) ad[i] = as[i];
        if(t < NU){ c_s[t] = g_c[b*NU+t]; lg_s[t] = g_lg[b*NU+t]; }
        else if(t < NU+MS) corr_s[t-NU] = inp[b*INC + NU + (t-NU)];
    }
    __syncthreads();

    int rg = t>>5, cg = t&31;            // 8 row-groups (8 m each) x 32 col-groups (4 n each)
    float acc[8][4];
    #pragma unroll
    for(int i=0;i<8;i++){ acc[i][0]=0.f; acc[i][1]=0.f; acc[i][2]=0.f; acc[i][3]=0.f; }

    #pragma unroll 4
    for(int k=0; k<NU; k++){
        float4 w = *(const float4*)&Ws[k][cg*4];
        #pragma unroll
        for(int i=0; i<8; i++){
            float a = A[rg*8+i][k];
            acc[i][0]=fmaf(a,w.x,acc[i][0]);
            acc[i][1]=fmaf(a,w.y,acc[i][1]);
            acc[i][2]=fmaf(a,w.z,acc[i][2]);
            acc[i][3]=fmaf(a,w.w,acc[i][3]);
        }
    }

    float htp[4] = {0.f,0.f,0.f,0.f};
    float* oh = out + (size_t)2*gridDim.x + (size_t)b*MS*NU;
    #pragma unroll
    for(int i=0; i<8; i++){
        int m = rg*8 + i;
        float cr = corr_s[m];
        float hv[4];
        #pragma unroll
        for(int j=0; j<4; j++){
            int n = cg*4 + j;
            float fg = sigmoidf(acc[i][j] + c_s[n]);
            float h  = A[m][n]*fg + cr*lg_s[n];
            hv[j] = h;
            htp[j] = fmaf(cr, h, htp[j]);
        }
        *(float4*)&oh[m*NU + cg*4] = make_float4(hv[0],hv[1],hv[2],hv[3]);
    }
    #pragma unroll
    for(int j=0;j<4;j++) htr[rg][cg*4+j] = htp[j];
    __syncthreads();
    if(t < NU){
        float s = 0.f;
        #pragma unroll
        for(int r=0;r<8;r++) s += htr[r][t];
        g_htilde[b*NU + t] = s;
    }
}

// ---------------- K5: after_preds, improve, result ----------------
__global__ __launch_bounds__(256) void k5_out(const float* __restrict__ inp,
                                              const float* __restrict__ outW,
                                              const float* __restrict__ outb,
                                              float* __restrict__ out){
    __shared__ float ht[16][NU], tp[16][NU];
    __shared__ __align__(16) float Ws[32][NU];
    int t = threadIdx.x, row = t>>4, cg = t&15;
    int b0 = blockIdx.x*16, b = b0 + row;
    for(int i=t; i<16*NU; i+=256){
        int r = i>>7, c = i&127;
        ht[r][c] = g_htilde[(b0+r)*NU + c];
        tp[r][c] = inp[(b0+r)*INC + NU + MS + c];
    }
    __syncthreads();
    float acc[8];
    #pragma unroll
    for(int j=0;j<8;j++) acc[j]=0.f;
    gemm16(ht, outW,         Ws, row, cg, acc);
    gemm16(tp, outW + NU*NU, Ws, row, cg, acc);
    float s = 0.f;
    #pragma unroll
    for(int j=0;j<8;j++) s += sigmoidf(acc[j] + outb[cg*8+j]);
    for(int o=8;o>0;o>>=1) s += __shfl_xor_sync(0xffffffffu, s, o, 16);
    if(cg==0){
        float p  = g_preds[b];
        float ap = s * (1.f/NU);
        out[b*2]     = p;
        out[b*2 + 1] = (ap - p) / (1.f - p);
    }
}

// ---------------- launch ----------------
extern "C" void kernel_launch(void* const* d_in, const int* in_sizes, int n_in,
                              void* d_out, int out_size){
    const float* inp    = (const float*)d_in[0];
    const float* states = (const float*)d_in[1];
    const float* tw     = (const float*)d_in[2];
    const float* aw     = (const float*)d_in[3];
    const float* hw     = (const float*)d_in[4];
    const float* Wf     = (const float*)d_in[5];
    const float* bias   = (const float*)d_in[6];
    const float* g3W    = (const float*)d_in[7];
    const float* g3b    = (const float*)d_in[8];
    const float* outW   = (const float*)d_in[9];
    const float* outb   = (const float*)d_in[10];
    const float* tgW    = (const float*)d_in[11];
    const float* tgb    = (const float*)d_in[12];
    const float* agW    = (const float*)d_in[13];
    const float* agb    = (const float*)d_in[14];
    const float* hgW    = (const float*)d_in[15];
    const float* hgb    = (const float*)d_in[16];
    float* out = (float*)d_out;
    int B = in_sizes[0] / INC;

    size_t smem4 = (size_t)(NU*NU + MS*NU + 2*NU + MS + 8*NU) * sizeof(float); // 103,680 B
    cudaFuncSetAttribute(k4_main, cudaFuncAttributeMaxDynamicSharedMemorySize, (int)smem4);

    k0_wsum <<<1, 128>>>(g3W);
    k1_hpt  <<<B, 128>>>(inp, states);
    k2_vec  <<<B/16, 256>>>(inp, outW, outb, tgW, tgb, agW, agb, hgW, hgb, g3W, g3b);
    k3_fusion<<<B/16, 256>>>(tw, aw, hw, Wf, bias);
    k4_main <<<B, 256, smem4>>>(inp, states, g3W, out);
    k5_out  <<<B/16, 256>>>(inp, outW, outb, out);
}

// round 4
// speedup vs baseline: 1.2593x; 1.2593x over previous
#include <cuda_runtime.h>
#include <cuda_bf16.h>
#include <cstdint>

#define NU   128
#define MS   64
#define INC  323          // [0:128) interact | [128:192) corr | [192:320) topic | 320 t | 321 a | 322 h
#define BMAX 4096
#define TB   32           // batches per block in k23/k5

// ---------------- scratch (device globals; no allocation) ----------------
__device__ float g_hpt  [BMAX*NU];
__device__ float g_lg   [BMAX*NU];
__device__ float g_c    [BMAX*NU];
__device__ float g_preds[BMAX];
__device__ float g_ws   [3*NU];
__device__ __nv_bfloat16 g_w1hi[NU*NU];   // W1^T hi: row n, swizzled, 256B row stride
__device__ __nv_bfloat16 g_w1lo[NU*NU];   // W1^T lo

__device__ __forceinline__ float sigmoidf(float x){ return 1.f/(1.f+__expf(-x)); }

// swizzled byte offset within a [rows][128] bf16 tile, 256B row stride.
// XOR of byte bits [6:4] with (row&7) -> conflict-free LDS for mma fragment patterns.
__device__ __forceinline__ int swzA(int row, int cb){ return row*256 + (cb ^ ((row&7)<<4)); }

#define MMA16816(c, a, b0v, b1v) \
    asm volatile("mma.sync.aligned.m16n8k16.row.col.f32.bf16.bf16.f32 " \
        "{%0,%1,%2,%3}, {%4,%5,%6,%7}, {%8,%9}, {%0,%1,%2,%3};" \
        : "+f"((c)[0]), "+f"((c)[1]), "+f"((c)[2]), "+f"((c)[3]) \
        : "r"((a)[0]), "r"((a)[1]), "r"((a)[2]), "r"((a)[3]), "r"(b0v), "r"(b1v))

// ---------------- K0: colsums of gate3_W factor rows ----------------
__global__ void k0_wsum(const float* __restrict__ g3W){
    int n = threadIdx.x;
    #pragma unroll
    for(int g=0; g<3; g++){
        float s = 0.f;
        for(int u=0; u<50; u++) s += g3W[(256 + g*50 + u)*NU + n];
        g_ws[g*NU + n] = s;
    }
}

// ---------------- K0b: split-transpose gate3_W[0:128] -> bf16 hi/lo, swizzled ----------------
__global__ __launch_bounds__(256) void k0b_wsplit(const float* __restrict__ g3W){
    int id = blockIdx.x*256 + threadIdx.x;     // 16384 threads
    int n = id >> 7, k = id & 127;
    float v = g3W[k*NU + n];                   // W^T[n][k]
    __nv_bfloat16 hi = __float2bfloat16(v);
    __nv_bfloat16 lo = __float2bfloat16(v - __bfloat162float(hi));
    int off = swzA(n, 2*k);
    *(__nv_bfloat16*)((char*)g_w1hi + off) = hi;
    *(__nv_bfloat16*)((char*)g_w1lo + off) = lo;
}

// ---------------- K1: h_pre_tilde ----------------
__global__ __launch_bounds__(128) void k1_hpt(const float* __restrict__ inp,
                                              const float* __restrict__ states){
    int b = blockIdx.x, n = threadIdx.x;
    __shared__ float corr[MS];
    if(n < MS) corr[n] = inp[(size_t)b*INC + NU + n];
    __syncthreads();
    const float* hp = states + (size_t)b*MS*NU;
    float a0=0.f,a1=0.f,a2=0.f,a3=0.f;
    #pragma unroll
    for(int m=0; m<MS; m+=4){
        a0 = fmaf(corr[m+0], hp[(m+0)*NU + n], a0);
        a1 = fmaf(corr[m+1], hp[(m+1)*NU + n], a1);
        a2 = fmaf(corr[m+2], hp[(m+2)*NU + n], a2);
        a3 = fmaf(corr[m+3], hp[(m+3)*NU + n], a3);
    }
    g_hpt[b*NU + n] = (a0+a1)+(a2+a3);
}

// ================= register-tiled GEMM core =================
__device__ __forceinline__ void gemm_rt(const float (*A)[NU], const float* __restrict__ W,
                                        float (*Ws)[NU], int rg, int cg, float acc[4][4]){
    int t = threadIdx.x;
    #pragma unroll 1
    for(int kt=0; kt<4; kt++){
        __syncthreads();
        const float4* src = (const float4*)(W + kt*32*NU);
        float4* dst = (float4*)Ws;
        #pragma unroll
        for(int i=0;i<4;i++) dst[t + i*256] = src[t + i*256];
        __syncthreads();
        #pragma unroll
        for(int k=0; k<32; k+=4){
            float4 w0 = *(const float4*)&Ws[k+0][cg*4];
            float4 w1 = *(const float4*)&Ws[k+1][cg*4];
            float4 w2 = *(const float4*)&Ws[k+2][cg*4];
            float4 w3 = *(const float4*)&Ws[k+3][cg*4];
            #pragma unroll
            for(int i=0;i<4;i++){
                float4 a = *(const float4*)&A[rg*4+i][kt*32+k];
                acc[i][0]=fmaf(a.x,w0.x,fmaf(a.y,w1.x,fmaf(a.z,w2.x,fmaf(a.w,w3.x,acc[i][0]))));
                acc[i][1]=fmaf(a.x,w0.y,fmaf(a.y,w1.y,fmaf(a.z,w2.y,fmaf(a.w,w3.y,acc[i][1]))));
                acc[i][2]=fmaf(a.x,w0.z,fmaf(a.y,w1.z,fmaf(a.z,w2.z,fmaf(a.w,w3.z,acc[i][2]))));
                acc[i][3]=fmaf(a.x,w0.w,fmaf(a.y,w1.w,fmaf(a.z,w2.w,fmaf(a.w,w3.w,acc[i][3]))));
            }
        }
    }
}

// ---------------- K23: preds + gates + c + fusion ----------------
struct SM23 {
    float A0[TB][NU];
    float A1[TB][NU];
    float A2[TB][NU];
    float GA[3][TB][NU];
    float Ws[32][NU];
    float fact[TB][4];
    float Wf_s[4];
};

__global__ __launch_bounds__(256) void k23(const float* __restrict__ inp,
    const float* __restrict__ outW, const float* __restrict__ outb,
    const float* __restrict__ tgW,  const float* __restrict__ tgb,
    const float* __restrict__ agW,  const float* __restrict__ agb,
    const float* __restrict__ hgW,  const float* __restrict__ hgb,
    const float* __restrict__ g3W,  const float* __restrict__ g3b,
    const float* __restrict__ tw,   const float* __restrict__ aw, const float* __restrict__ hw,
    const float* __restrict__ Wf,   const float* __restrict__ bias){

    extern __shared__ char smraw[];
    SM23& S = *(SM23*)smraw;
    int t = threadIdx.x, rg = t>>5, cg = t&31;
    int b0 = blockIdx.x*TB;

    for(int i=t; i<TB*NU; i+=256){
        int r = i>>7, c = i&127;
        S.A0[r][c] = g_hpt[(b0+r)*NU + c];
        S.A1[r][c] = inp[(size_t)(b0+r)*INC + c];
        S.A2[r][c] = inp[(size_t)(b0+r)*INC + NU + MS + c];
    }
    for(int i=t; i<TB*3; i+=256){ int r=i/3, g=i%3; S.fact[r][g] = inp[(size_t)(b0+r)*INC + 320 + g]; }
    if(t<4) S.Wf_s[t] = Wf[t];

    float acc[4][4];

    // ---- preds ----
    #pragma unroll
    for(int i=0;i<4;i++){ acc[i][0]=acc[i][1]=acc[i][2]=acc[i][3]=0.f; }
    gemm_rt(S.A0, outW,        S.Ws, rg, cg, acc);
    gemm_rt(S.A2, outW + NU*NU,S.Ws, rg, cg, acc);
    {
        float s[4];
        #pragma unroll
        for(int i=0;i<4;i++){
            s[i] = 0.f;
            #pragma unroll
            for(int j=0;j<4;j++) s[i] += sigmoidf(acc[i][j] + outb[cg*4+j]);
        }
        #pragma unroll
        for(int off=16; off; off>>=1){
            #pragma unroll
            for(int i=0;i<4;i++) s[i] += __shfl_xor_sync(0xffffffffu, s[i], off);
        }
        if(cg==0){
            #pragma unroll
            for(int i=0;i<4;i++) g_preds[b0 + rg*4 + i] = s[i] * (1.f/NU);
        }
    }

    // ---- three gates ----
    const float* Wg[3] = {tgW, agW, hgW};
    const float* bg[3] = {tgb, agb, hgb};
    #pragma unroll 1
    for(int g=0; g<3; g++){
        #pragma unroll
        for(int i=0;i<4;i++){ acc[i][0]=acc[i][1]=acc[i][2]=acc[i][3]=0.f; }
        gemm_rt(S.A0, Wg[g],         S.Ws, rg, cg, acc);
        gemm_rt(S.A1, Wg[g] + NU*NU, S.Ws, rg, cg, acc);
        #pragma unroll
        for(int i=0;i<4;i++){
            float f = S.fact[rg*4+i][g];
            float gain = 0.3f + 0.7f*sigmoidf(10.f*(f - 0.3f));
            #pragma unroll
            for(int j=0;j<4;j++)
                S.GA[g][rg*4+i][cg*4+j] = sigmoidf((acc[i][j] + bg[g][cg*4+j]) * gain);
        }
    }

    // ---- c = interact @ g3W[128:256] + factors ----
    #pragma unroll
    for(int i=0;i<4;i++){ acc[i][0]=acc[i][1]=acc[i][2]=acc[i][3]=0.f; }
    gemm_rt(S.A1, g3W + NU*NU, S.Ws, rg, cg, acc);
    #pragma unroll
    for(int i=0;i<4;i++){
        int b = b0 + rg*4 + i;
        float f0=S.fact[rg*4+i][0], f1=S.fact[rg*4+i][1], f2=S.fact[rg*4+i][2];
        #pragma unroll
        for(int j=0;j<4;j++){
            int n = cg*4 + j;
            g_c[b*NU + n] = acc[i][j] + f0*g_ws[n] + f1*g_ws[NU+n] + f2*g_ws[2*NU+n] + g3b[n];
        }
    }

    // ---- fusion ----
    const float* Wr[3] = {tw, aw, hw};
    float fus[4][4];
    #pragma unroll
    for(int i=0;i<4;i++){ fus[i][0]=fus[i][1]=fus[i][2]=fus[i][3]=0.f; }
    #pragma unroll 1
    for(int r=0; r<4; r++){
        float prod[4][4];
        #pragma unroll 1
        for(int g=0; g<3; g++){
            #pragma unroll
            for(int i=0;i<4;i++){ acc[i][0]=acc[i][1]=acc[i][2]=acc[i][3]=0.f; }
            gemm_rt(S.GA[g], Wr[g] + (size_t)r*129*NU, S.Ws, rg, cg, acc);
            #pragma unroll
            for(int i=0;i<4;i++)
                #pragma unroll
                for(int j=0;j<4;j++)
                    acc[i][j] += Wr[g][((size_t)r*129 + 128)*NU + cg*4 + j];
            if(g==0){
                #pragma unroll
                for(int i=0;i<4;i++) for(int j=0;j<4;j++) prod[i][j] = acc[i][j];
            } else {
                #pragma unroll
                for(int i=0;i<4;i++) for(int j=0;j<4;j++) prod[i][j] *= acc[i][j];
            }
        }
        float wf = S.Wf_s[r];
        #pragma unroll
        for(int i=0;i<4;i++) for(int j=0;j<4;j++) fus[i][j] = fmaf(wf, prod[i][j], fus[i][j]);
    }
    #pragma unroll
    for(int i=0;i<4;i++){
        int b = b0 + rg*4 + i;
        float4 o;
        o.x = fmaxf(fus[i][0] + bias[cg*4+0], 0.f);
        o.y = fmaxf(fus[i][1] + bias[cg*4+1], 0.f);
        o.z = fmaxf(fus[i][2] + bias[cg*4+2], 0.f);
        o.w = fmaxf(fus[i][3] + bias[cg*4+3], 0.f);
        *(float4*)&g_lg[b*NU + cg*4] = o;
    }
}

// ---------------- K4: mma.sync forget-gate GEMM + fused state update ----------------
// One CTA per batch: [64,128] @ W1[128,128] with bf16 hi/lo 3-term split.
#define SM4_AHI 0
#define SM4_ALO 16384
#define SM4_WHI 32768
#define SM4_WLO 65536
#define SM4_AUX 98304
#define SM4_TOTAL (98304 + 1280)

__global__ __launch_bounds__(128)
void k4_main(const float* __restrict__ inp, const float* __restrict__ states,
             float* __restrict__ out, int B){
    extern __shared__ char sm[];
    float* corr_s = (float*)(sm + SM4_AUX);          // 64
    float* c_s    = (float*)(sm + SM4_AUX + 256);    // 128
    float* lg_s   = (float*)(sm + SM4_AUX + 768);    // 128

    int t = threadIdx.x, w = t>>5, l = t&31;
    int b = blockIdx.x;

    // stage W hi/lo (already transposed+split+swizzled)
    {
        const uint4* sh = (const uint4*)g_w1hi;
        const uint4* sl = (const uint4*)g_w1lo;
        uint4* dh = (uint4*)(sm + SM4_WHI);
        uint4* dl = (uint4*)(sm + SM4_WLO);
        for(int i=t; i<2048; i+=128){ dh[i]=sh[i]; dl[i]=sl[i]; }
    }
    // stage + split A = states[b] (64 x 128)
    {
        const float4* As = (const float4*)(states + (size_t)b*MS*NU);
        for(int f=t; f<2048; f+=128){
            int row = f>>5, cq = f&31;
            float4 v = As[f];
            __nv_bfloat16 h0=__float2bfloat16(v.x), h1=__float2bfloat16(v.y),
                          h2=__float2bfloat16(v.z), h3=__float2bfloat16(v.w);
            __nv_bfloat16 l0=__float2bfloat16(v.x-__bfloat162float(h0));
            __nv_bfloat16 l1=__float2bfloat16(v.y-__bfloat162float(h1));
            __nv_bfloat16 l2=__float2bfloat16(v.z-__bfloat162float(h2));
            __nv_bfloat16 l3=__float2bfloat16(v.w-__bfloat162float(h3));
            uint2 hv, lv;
            hv.x = (uint32_t)__bfloat16_as_ushort(h0) | ((uint32_t)__bfloat16_as_ushort(h1)<<16);
            hv.y = (uint32_t)__bfloat16_as_ushort(h2) | ((uint32_t)__bfloat16_as_ushort(h3)<<16);
            lv.x = (uint32_t)__bfloat16_as_ushort(l0) | ((uint32_t)__bfloat16_as_ushort(l1)<<16);
            lv.y = (uint32_t)__bfloat16_as_ushort(l2) | ((uint32_t)__bfloat16_as_ushort(l3)<<16);
            int off = swzA(row, cq*8);
            *(uint2*)(sm + SM4_AHI + off) = hv;
            *(uint2*)(sm + SM4_ALO + off) = lv;
        }
    }
    if(t < MS) corr_s[t] = inp[(size_t)b*INC + NU + t];
    if(t < NU){ c_s[t] = g_c[(size_t)b*NU + t]; lg_s[t] = g_lg[(size_t)b*NU + t]; }
    __syncthreads();

    // ---- mma mainloop: warp tile = rows [w*16, w*16+16) x all 128 cols ----
    int g = l>>2, tt = l&3;
    int r0 = w*16;
    float acc[16][4];
    #pragma unroll
    for(int nt=0; nt<16; nt++){ acc[nt][0]=acc[nt][1]=acc[nt][2]=acc[nt][3]=0.f; }

    #pragma unroll 1
    for(int kt=0; kt<8; kt++){
        int cb0 = kt*32 + tt*4, cb1 = cb0 + 16;
        uint32_t ah[4], al[4];
        ah[0] = *(const uint32_t*)(sm + SM4_AHI + swzA(r0+g,   cb0));
        ah[1] = *(const uint32_t*)(sm + SM4_AHI + swzA(r0+g+8, cb0));
        ah[2] = *(const uint32_t*)(sm + SM4_AHI + swzA(r0+g,   cb1));
        ah[3] = *(const uint32_t*)(sm + SM4_AHI + swzA(r0+g+8, cb1));
        al[0] = *(const uint32_t*)(sm + SM4_ALO + swzA(r0+g,   cb0));
        al[1] = *(const uint32_t*)(sm + SM4_ALO + swzA(r0+g+8, cb0));
        al[2] = *(const uint32_t*)(sm + SM4_ALO + swzA(r0+g,   cb1));
        al[3] = *(const uint32_t*)(sm + SM4_ALO + swzA(r0+g+8, cb1));
        #pragma unroll
        for(int nt=0; nt<16; nt++){
            uint32_t bh0 = *(const uint32_t*)(sm + SM4_WHI + swzA(nt*8+g, cb0));
            uint32_t bh1 = *(const uint32_t*)(sm + SM4_WHI + swzA(nt*8+g, cb1));
            uint32_t bl0 = *(const uint32_t*)(sm + SM4_WLO + swzA(nt*8+g, cb0));
            uint32_t bl1 = *(const uint32_t*)(sm + SM4_WLO + swzA(nt*8+g, cb1));
            MMA16816(acc[nt], ah, bh0, bh1);
            MMA16816(acc[nt], al, bh0, bh1);
            MMA16816(acc[nt], ah, bl0, bl1);
        }
    }

    // ---- epilogue from fragments ----
    float* hout = out + (size_t)2*B + (size_t)b*MS*NU;
    int m0 = r0 + g, m1 = r0 + g + 8;
    float cr0 = corr_s[m0], cr1 = corr_s[m1];
    #pragma unroll
    for(int nt=0; nt<16; nt++){
        int n0 = nt*8 + tt*2;
        float2 cc = *(const float2*)(c_s + n0);
        float2 ll = *(const float2*)(lg_s + n0);
        // row m0
        {
            uint32_t sh = *(const uint32_t*)(sm + SM4_AHI + swzA(m0, n0*2));
            uint32_t sl = *(const uint32_t*)(sm + SM4_ALO + swzA(m0, n0*2));
            float s0 = __uint_as_float(sh<<16) + __uint_as_float(sl<<16);
            float s1 = __uint_as_float(sh & 0xffff0000u) + __uint_as_float(sl & 0xffff0000u);
            float2 o;
            o.x = s0 * sigmoidf(acc[nt][0] + cc.x) + cr0*ll.x;
            o.y = s1 * sigmoidf(acc[nt][1] + cc.y) + cr0*ll.y;
            *(float2*)(hout + (size_t)m0*NU + n0) = o;
        }
        // row m1
        {
            uint32_t sh = *(const uint32_t*)(sm + SM4_AHI + swzA(m1, n0*2));
            uint32_t sl = *(const uint32_t*)(sm + SM4_ALO + swzA(m1, n0*2));
            float s0 = __uint_as_float(sh<<16) + __uint_as_float(sl<<16);
            float s1 = __uint_as_float(sh & 0xffff0000u) + __uint_as_float(sl & 0xffff0000u);
            float2 o;
            o.x = s0 * sigmoidf(acc[nt][2] + cc.x) + cr1*ll.x;
            o.y = s1 * sigmoidf(acc[nt][3] + cc.y) + cr1*ll.y;
            *(float2*)(hout + (size_t)m1*NU + n0) = o;
        }
    }
}

// ---------------- K5: h_tilde + after_preds + result ----------------
struct SM5 {
    float corr[TB][MS];
    float ht[TB][NU];
    float tp[TB][NU];
    float Ws[32][NU];
};

__global__ __launch_bounds__(256) void k5_out(const float* __restrict__ inp,
                                              const float* __restrict__ outW,
                                              const float* __restrict__ outb,
                                              float* __restrict__ out, int B){
    extern __shared__ char smraw[];
    SM5& S = *(SM5*)smraw;
    int t = threadIdx.x, rg = t>>5, cg = t&31;
    int b0 = blockIdx.x*TB;

    for(int i=t; i<TB*MS; i+=256){ int r=i>>6, m=i&63; S.corr[r][m] = inp[(size_t)(b0+r)*INC + NU + m]; }
    for(int i=t; i<TB*NU; i+=256){ int r=i>>7, c=i&127; S.tp[r][c] = inp[(size_t)(b0+r)*INC + NU + MS + c]; }
    __syncthreads();

    const float* hbase = out + (size_t)2*B;
    #pragma unroll 1
    for(int p=0; p<16; p++){
        int r = (t>>7) + p*2, c = t&127;
        const float* hb = hbase + (size_t)(b0+r)*MS*NU + c;
        float a0=0.f, a1=0.f;
        #pragma unroll
        for(int m=0; m<MS; m+=2){
            a0 = fmaf(S.corr[r][m+0], hb[(m+0)*NU], a0);
            a1 = fmaf(S.corr[r][m+1], hb[(m+1)*NU], a1);
        }
        S.ht[r][c] = a0 + a1;
    }

    float acc[4][4];
    #pragma unroll
    for(int i=0;i<4;i++){ acc[i][0]=acc[i][1]=acc[i][2]=acc[i][3]=0.f; }
    gemm_rt(S.ht, outW,         S.Ws, rg, cg, acc);
    gemm_rt(S.tp, outW + NU*NU, S.Ws, rg, cg, acc);

    float s[4];
    #pragma unroll
    for(int i=0;i<4;i++){
        s[i]=0.f;
        #pragma unroll
        for(int j=0;j<4;j++) s[i] += sigmoidf(acc[i][j] + outb[cg*4+j]);
    }
    #pragma unroll
    for(int off=16; off; off>>=1){
        #pragma unroll
        for(int i=0;i<4;i++) s[i] += __shfl_xor_sync(0xffffffffu, s[i], off);
    }
    if(cg==0){
        #pragma unroll
        for(int i=0;i<4;i++){
            int b = b0 + rg*4 + i;
            float p  = g_preds[b];
            float ap = s[i] * (1.f/NU);
            out[(size_t)b*2]     = p;
            out[(size_t)b*2 + 1] = (ap - p) / (1.f - p);
        }
    }
}

// ---------------- launch ----------------
extern "C" void kernel_launch(void* const* d_in, const int* in_sizes, int n_in,
                              void* d_out, int out_size){
    const float* inp    = (const float*)d_in[0];
    const float* states = (const float*)d_in[1];
    const float* tw     = (const float*)d_in[2];
    const float* aw     = (const float*)d_in[3];
    const float* hw     = (const float*)d_in[4];
    const float* Wf     = (const float*)d_in[5];
    const float* bias   = (const float*)d_in[6];
    const float* g3W    = (const float*)d_in[7];
    const float* g3b    = (const float*)d_in[8];
    const float* outW   = (const float*)d_in[9];
    const float* outb   = (const float*)d_in[10];
    const float* tgW    = (const float*)d_in[11];
    const float* tgb    = (const float*)d_in[12];
    const float* agW    = (const float*)d_in[13];
    const float* agb    = (const float*)d_in[14];
    const float* hgW    = (const float*)d_in[15];
    const float* hgb    = (const float*)d_in[16];
    float* out = (float*)d_out;
    int B = in_sizes[0] / INC;

    cudaFuncSetAttribute(k23,     cudaFuncAttributeMaxDynamicSharedMemorySize, (int)sizeof(SM23));
    cudaFuncSetAttribute(k4_main, cudaFuncAttributeMaxDynamicSharedMemorySize, SM4_TOTAL);
    cudaFuncSetAttribute(k5_out,  cudaFuncAttributeMaxDynamicSharedMemorySize, (int)sizeof(SM5));

    k0_wsum   <<<1, 128>>>(g3W);
    k0b_wsplit<<<64, 256>>>(g3W);
    k1_hpt    <<<B, 128>>>(inp, states);
    k23       <<<B/TB, 256, sizeof(SM23)>>>(inp, outW, outb, tgW, tgb, agW, agb, hgW, hgb,
                                            g3W, g3b, tw, aw, hw, Wf, bias);
    k4_main   <<<B, 128, SM4_TOTAL>>>(inp, states, out, B);
    k5_out    <<<B/TB, 256, sizeof(SM5)>>>(inp, outW, outb, out, B);
}

// round 5
// speedup vs baseline: 1.2796x; 1.0161x over previous
#include <cuda_runtime.h>
#include <cuda_bf16.h>
#include <cstdint>

#define NU   128
#define MS   64
#define INC  323          // [0:128) interact | [128:192) corr | [192:320) topic | 320 t | 321 a | 322 h
#define BMAX 4096
#define TB   32           // batches per block in k23/k5

// ---------------- scratch (device globals; no allocation) ----------------
__device__ float g_hpt  [BMAX*NU];
__device__ float g_lg   [BMAX*NU];
__device__ float g_c    [BMAX*NU];
__device__ float g_preds[BMAX];
__device__ float g_ws   [3*NU];
__device__ __nv_bfloat16 g_w1hi[NU*NU];   // W1^T hi: row n, swizzled, 256B row stride
__device__ __nv_bfloat16 g_w1lo[NU*NU];   // W1^T lo

__device__ __forceinline__ float sigmoidf(float x){ return 1.f/(1.f+__expf(-x)); }

// swizzled byte offset within a [rows][128] bf16 tile, 256B row stride.
// XOR of byte bits [6:4] with (row&7) -> conflict-free LDS for mma fragment patterns.
__device__ __forceinline__ int swzA(int row, int cb){ return row*256 + (cb ^ ((row&7)<<4)); }

#define MMA16816(c, a, b0v, b1v) \
    asm volatile("mma.sync.aligned.m16n8k16.row.col.f32.bf16.bf16.f32 " \
        "{%0,%1,%2,%3}, {%4,%5,%6,%7}, {%8,%9}, {%0,%1,%2,%3};" \
        : "+f"((c)[0]), "+f"((c)[1]), "+f"((c)[2]), "+f"((c)[3]) \
        : "r"((a)[0]), "r"((a)[1]), "r"((a)[2]), "r"((a)[3]), "r"(b0v), "r"(b1v))

// ---------------- K0: colsums of gate3_W factor rows ----------------
__global__ void k0_wsum(const float* __restrict__ g3W){
    int n = threadIdx.x;
    #pragma unroll
    for(int g=0; g<3; g++){
        float s = 0.f;
        for(int u=0; u<50; u++) s += g3W[(256 + g*50 + u)*NU + n];
        g_ws[g*NU + n] = s;
    }
}

// ---------------- K0b: split-transpose gate3_W[0:128] -> bf16 hi/lo, swizzled ----------------
__global__ __launch_bounds__(256) void k0b_wsplit(const float* __restrict__ g3W){
    int id = blockIdx.x*256 + threadIdx.x;     // 16384 threads
    int n = id >> 7, k = id & 127;
    float v = g3W[k*NU + n];                   // W^T[n][k]
    __nv_bfloat16 hi = __float2bfloat16(v);
    __nv_bfloat16 lo = __float2bfloat16(v - __bfloat162float(hi));
    int off = swzA(n, 2*k);
    *(__nv_bfloat16*)((char*)g_w1hi + off) = hi;
    *(__nv_bfloat16*)((char*)g_w1lo + off) = lo;
}

// ---------------- K1: h_pre_tilde ----------------
__global__ __launch_bounds__(128) void k1_hpt(const float* __restrict__ inp,
                                              const float* __restrict__ states){
    int b = blockIdx.x, n = threadIdx.x;
    __shared__ float corr[MS];
    if(n < MS) corr[n] = inp[(size_t)b*INC + NU + n];
    __syncthreads();
    const float* hp = states + (size_t)b*MS*NU;
    float a0=0.f,a1=0.f,a2=0.f,a3=0.f;
    #pragma unroll
    for(int m=0; m<MS; m+=4){
        a0 = fmaf(corr[m+0], hp[(m+0)*NU + n], a0);
        a1 = fmaf(corr[m+1], hp[(m+1)*NU + n], a1);
        a2 = fmaf(corr[m+2], hp[(m+2)*NU + n], a2);
        a3 = fmaf(corr[m+3], hp[(m+3)*NU + n], a3);
    }
    g_hpt[b*NU + n] = (a0+a1)+(a2+a3);
}

// ================= register-tiled GEMM core =================
__device__ __forceinline__ void gemm_rt(const float (*A)[NU], const float* __restrict__ W,
                                        float (*Ws)[NU], int rg, int cg, float acc[4][4]){
    int t = threadIdx.x;
    #pragma unroll 1
    for(int kt=0; kt<4; kt++){
        __syncthreads();
        const float4* src = (const float4*)(W + kt*32*NU);
        float4* dst = (float4*)Ws;
        #pragma unroll
        for(int i=0;i<4;i++) dst[t + i*256] = src[t + i*256];
        __syncthreads();
        #pragma unroll
        for(int k=0; k<32; k+=4){
            float4 w0 = *(const float4*)&Ws[k+0][cg*4];
            float4 w1 = *(const float4*)&Ws[k+1][cg*4];
            float4 w2 = *(const float4*)&Ws[k+2][cg*4];
            float4 w3 = *(const float4*)&Ws[k+3][cg*4];
            #pragma unroll
            for(int i=0;i<4;i++){
                float4 a = *(const float4*)&A[rg*4+i][kt*32+k];
                acc[i][0]=fmaf(a.x,w0.x,fmaf(a.y,w1.x,fmaf(a.z,w2.x,fmaf(a.w,w3.x,acc[i][0]))));
                acc[i][1]=fmaf(a.x,w0.y,fmaf(a.y,w1.y,fmaf(a.z,w2.y,fmaf(a.w,w3.y,acc[i][1]))));
                acc[i][2]=fmaf(a.x,w0.z,fmaf(a.y,w1.z,fmaf(a.z,w2.z,fmaf(a.w,w3.z,acc[i][2]))));
                acc[i][3]=fmaf(a.x,w0.w,fmaf(a.y,w1.w,fmaf(a.z,w2.w,fmaf(a.w,w3.w,acc[i][3]))));
            }
        }
    }
}

// ---------------- K23: preds + gates + c + fusion ----------------
struct SM23 {
    float A0[TB][NU];
    float A1[TB][NU];
    float A2[TB][NU];
    float GA[3][TB][NU];
    float Ws[32][NU];
    float fact[TB][4];
    float Wf_s[4];
};

__global__ __launch_bounds__(256) void k23(const float* __restrict__ inp,
    const float* __restrict__ outW, const float* __restrict__ outb,
    const float* __restrict__ tgW,  const float* __restrict__ tgb,
    const float* __restrict__ agW,  const float* __restrict__ agb,
    const float* __restrict__ hgW,  const float* __restrict__ hgb,
    const float* __restrict__ g3W,  const float* __restrict__ g3b,
    const float* __restrict__ tw,   const float* __restrict__ aw, const float* __restrict__ hw,
    const float* __restrict__ Wf,   const float* __restrict__ bias){

    extern __shared__ char smraw[];
    SM23& S = *(SM23*)smraw;
    int t = threadIdx.x, rg = t>>5, cg = t&31;
    int b0 = blockIdx.x*TB;

    for(int i=t; i<TB*NU; i+=256){
        int r = i>>7, c = i&127;
        S.A0[r][c] = g_hpt[(b0+r)*NU + c];
        S.A1[r][c] = inp[(size_t)(b0+r)*INC + c];
        S.A2[r][c] = inp[(size_t)(b0+r)*INC + NU + MS + c];
    }
    for(int i=t; i<TB*3; i+=256){ int r=i/3, g=i%3; S.fact[r][g] = inp[(size_t)(b0+r)*INC + 320 + g]; }
    if(t<4) S.Wf_s[t] = Wf[t];

    float acc[4][4];

    // ---- preds ----
    #pragma unroll
    for(int i=0;i<4;i++){ acc[i][0]=acc[i][1]=acc[i][2]=acc[i][3]=0.f; }
    gemm_rt(S.A0, outW,        S.Ws, rg, cg, acc);
    gemm_rt(S.A2, outW + NU*NU,S.Ws, rg, cg, acc);
    {
        float s[4];
        #pragma unroll
        for(int i=0;i<4;i++){
            s[i] = 0.f;
            #pragma unroll
            for(int j=0;j<4;j++) s[i] += sigmoidf(acc[i][j] + outb[cg*4+j]);
        }
        #pragma unroll
        for(int off=16; off; off>>=1){
            #pragma unroll
            for(int i=0;i<4;i++) s[i] += __shfl_xor_sync(0xffffffffu, s[i], off);
        }
        if(cg==0){
            #pragma unroll
            for(int i=0;i<4;i++) g_preds[b0 + rg*4 + i] = s[i] * (1.f/NU);
        }
    }

    // ---- three gates ----
    const float* Wg[3] = {tgW, agW, hgW};
    const float* bg[3] = {tgb, agb, hgb};
    #pragma unroll 1
    for(int g=0; g<3; g++){
        #pragma unroll
        for(int i=0;i<4;i++){ acc[i][0]=acc[i][1]=acc[i][2]=acc[i][3]=0.f; }
        gemm_rt(S.A0, Wg[g],         S.Ws, rg, cg, acc);
        gemm_rt(S.A1, Wg[g] + NU*NU, S.Ws, rg, cg, acc);
        #pragma unroll
        for(int i=0;i<4;i++){
            float f = S.fact[rg*4+i][g];
            float gain = 0.3f + 0.7f*sigmoidf(10.f*(f - 0.3f));
            #pragma unroll
            for(int j=0;j<4;j++)
                S.GA[g][rg*4+i][cg*4+j] = sigmoidf((acc[i][j] + bg[g][cg*4+j]) * gain);
        }
    }

    // ---- c = interact @ g3W[128:256] + factors ----
    #pragma unroll
    for(int i=0;i<4;i++){ acc[i][0]=acc[i][1]=acc[i][2]=acc[i][3]=0.f; }
    gemm_rt(S.A1, g3W + NU*NU, S.Ws, rg, cg, acc);
    #pragma unroll
    for(int i=0;i<4;i++){
        int b = b0 + rg*4 + i;
        float f0=S.fact[rg*4+i][0], f1=S.fact[rg*4+i][1], f2=S.fact[rg*4+i][2];
        #pragma unroll
        for(int j=0;j<4;j++){
            int n = cg*4 + j;
            g_c[b*NU + n] = acc[i][j] + f0*g_ws[n] + f1*g_ws[NU+n] + f2*g_ws[2*NU+n] + g3b[n];
        }
    }

    // ---- fusion ----
    const float* Wr[3] = {tw, aw, hw};
    float fus[4][4];
    #pragma unroll
    for(int i=0;i<4;i++){ fus[i][0]=fus[i][1]=fus[i][2]=fus[i][3]=0.f; }
    #pragma unroll 1
    for(int r=0; r<4; r++){
        float prod[4][4];
        #pragma unroll 1
        for(int g=0; g<3; g++){
            #pragma unroll
            for(int i=0;i<4;i++){ acc[i][0]=acc[i][1]=acc[i][2]=acc[i][3]=0.f; }
            gemm_rt(S.GA[g], Wr[g] + (size_t)r*129*NU, S.Ws, rg, cg, acc);
            #pragma unroll
            for(int i=0;i<4;i++)
                #pragma unroll
                for(int j=0;j<4;j++)
                    acc[i][j] += Wr[g][((size_t)r*129 + 128)*NU + cg*4 + j];
            if(g==0){
                #pragma unroll
                for(int i=0;i<4;i++) for(int j=0;j<4;j++) prod[i][j] = acc[i][j];
            } else {
                #pragma unroll
                for(int i=0;i<4;i++) for(int j=0;j<4;j++) prod[i][j] *= acc[i][j];
            }
        }
        float wf = S.Wf_s[r];
        #pragma unroll
        for(int i=0;i<4;i++) for(int j=0;j<4;j++) fus[i][j] = fmaf(wf, prod[i][j], fus[i][j]);
    }
    #pragma unroll
    for(int i=0;i<4;i++){
        int b = b0 + rg*4 + i;
        float4 o;
        o.x = fmaxf(fus[i][0] + bias[cg*4+0], 0.f);
        o.y = fmaxf(fus[i][1] + bias[cg*4+1], 0.f);
        o.z = fmaxf(fus[i][2] + bias[cg*4+2], 0.f);
        o.w = fmaxf(fus[i][3] + bias[cg*4+3], 0.f);
        *(float4*)&g_lg[b*NU + cg*4] = o;
    }
}

// ---------------- K4: mma.sync forget-gate GEMM + fused state update ----------------
// One CTA per batch: [64,128] @ W1[128,128] with bf16 hi/lo 3-term split.
#define SM4_AHI 0
#define SM4_ALO 16384
#define SM4_WHI 32768
#define SM4_WLO 65536
#define SM4_AUX 98304
#define SM4_TOTAL (98304 + 1280)

__global__ __launch_bounds__(128)
void k4_main(const float* __restrict__ inp, const float* __restrict__ states,
             float* __restrict__ out, int B){
    extern __shared__ char sm[];
    float* corr_s = (float*)(sm + SM4_AUX);          // 64
    float* c_s    = (float*)(sm + SM4_AUX + 256);    // 128
    float* lg_s   = (float*)(sm + SM4_AUX + 768);    // 128

    int t = threadIdx.x, w = t>>5, l = t&31;
    int b = blockIdx.x;

    // stage W hi/lo (already transposed+split+swizzled)
    {
        const uint4* sh = (const uint4*)g_w1hi;
        const uint4* sl = (const uint4*)g_w1lo;
        uint4* dh = (uint4*)(sm + SM4_WHI);
        uint4* dl = (uint4*)(sm + SM4_WLO);
        for(int i=t; i<2048; i+=128){ dh[i]=sh[i]; dl[i]=sl[i]; }
    }
    // stage + split A = states[b] (64 x 128)
    {
        const float4* As = (const float4*)(states + (size_t)b*MS*NU);
        for(int f=t; f<2048; f+=128){
            int row = f>>5, cq = f&31;
            float4 v = As[f];
            __nv_bfloat16 h0=__float2bfloat16(v.x), h1=__float2bfloat16(v.y),
                          h2=__float2bfloat16(v.z), h3=__float2bfloat16(v.w);
            __nv_bfloat16 l0=__float2bfloat16(v.x-__bfloat162float(h0));
            __nv_bfloat16 l1=__float2bfloat16(v.y-__bfloat162float(h1));
            __nv_bfloat16 l2=__float2bfloat16(v.z-__bfloat162float(h2));
            __nv_bfloat16 l3=__float2bfloat16(v.w-__bfloat162float(h3));
            uint2 hv, lv;
            hv.x = (uint32_t)__bfloat16_as_ushort(h0) | ((uint32_t)__bfloat16_as_ushort(h1)<<16);
            hv.y = (uint32_t)__bfloat16_as_ushort(h2) | ((uint32_t)__bfloat16_as_ushort(h3)<<16);
            lv.x = (uint32_t)__bfloat16_as_ushort(l0) | ((uint32_t)__bfloat16_as_ushort(l1)<<16);
            lv.y = (uint32_t)__bfloat16_as_ushort(l2) | ((uint32_t)__bfloat16_as_ushort(l3)<<16);
            int off = swzA(row, cq*8);
            *(uint2*)(sm + SM4_AHI + off) = hv;
            *(uint2*)(sm + SM4_ALO + off) = lv;
        }
    }
    if(t < MS) corr_s[t] = inp[(size_t)b*INC + NU + t];
    if(t < NU){ c_s[t] = g_c[(size_t)b*NU + t]; lg_s[t] = g_lg[(size_t)b*NU + t]; }
    __syncthreads();

    // ---- mma mainloop: warp tile = rows [w*16, w*16+16) x all 128 cols ----
    int g = l>>2, tt = l&3;
    int r0 = w*16;
    float acc[16][4];
    #pragma unroll
    for(int nt=0; nt<16; nt++){ acc[nt][0]=acc[nt][1]=acc[nt][2]=acc[nt][3]=0.f; }

    #pragma unroll 1
    for(int kt=0; kt<8; kt++){
        int cb0 = kt*32 + tt*4, cb1 = cb0 + 16;
        uint32_t ah[4], al[4];
        ah[0] = *(const uint32_t*)(sm + SM4_AHI + swzA(r0+g,   cb0));
        ah[1] = *(const uint32_t*)(sm + SM4_AHI + swzA(r0+g+8, cb0));
        ah[2] = *(const uint32_t*)(sm + SM4_AHI + swzA(r0+g,   cb1));
        ah[3] = *(const uint32_t*)(sm + SM4_AHI + swzA(r0+g+8, cb1));
        al[0] = *(const uint32_t*)(sm + SM4_ALO + swzA(r0+g,   cb0));
        al[1] = *(const uint32_t*)(sm + SM4_ALO + swzA(r0+g+8, cb0));
        al[2] = *(const uint32_t*)(sm + SM4_ALO + swzA(r0+g,   cb1));
        al[3] = *(const uint32_t*)(sm + SM4_ALO + swzA(r0+g+8, cb1));
        #pragma unroll
        for(int nt=0; nt<16; nt++){
            uint32_t bh0 = *(const uint32_t*)(sm + SM4_WHI + swzA(nt*8+g, cb0));
            uint32_t bh1 = *(const uint32_t*)(sm + SM4_WHI + swzA(nt*8+g, cb1));
            uint32_t bl0 = *(const uint32_t*)(sm + SM4_WLO + swzA(nt*8+g, cb0));
            uint32_t bl1 = *(const uint32_t*)(sm + SM4_WLO + swzA(nt*8+g, cb1));
            MMA16816(acc[nt], ah, bh0, bh1);
            MMA16816(acc[nt], al, bh0, bh1);
            MMA16816(acc[nt], ah, bl0, bl1);
        }
    }

    // ---- epilogue from fragments ----
    float* hout = out + (size_t)2*B + (size_t)b*MS*NU;
    int m0 = r0 + g, m1 = r0 + g + 8;
    float cr0 = corr_s[m0], cr1 = corr_s[m1];
    #pragma unroll
    for(int nt=0; nt<16; nt++){
        int n0 = nt*8 + tt*2;
        float2 cc = *(const float2*)(c_s + n0);
        float2 ll = *(const float2*)(lg_s + n0);
        // row m0
        {
            uint32_t sh = *(const uint32_t*)(sm + SM4_AHI + swzA(m0, n0*2));
            uint32_t sl = *(const uint32_t*)(sm + SM4_ALO + swzA(m0, n0*2));
            float s0 = __uint_as_float(sh<<16) + __uint_as_float(sl<<16);
            float s1 = __uint_as_float(sh & 0xffff0000u) + __uint_as_float(sl & 0xffff0000u);
            float2 o;
            o.x = s0 * sigmoidf(acc[nt][0] + cc.x) + cr0*ll.x;
            o.y = s1 * sigmoidf(acc[nt][1] + cc.y) + cr0*ll.y;
            *(float2*)(hout + (size_t)m0*NU + n0) = o;
        }
        // row m1
        {
            uint32_t sh = *(const uint32_t*)(sm + SM4_AHI + swzA(m1, n0*2));
            uint32_t sl = *(const uint32_t*)(sm + SM4_ALO + swzA(m1, n0*2));
            float s0 = __uint_as_float(sh<<16) + __uint_as_float(sl<<16);
            float s1 = __uint_as_float(sh & 0xffff0000u) + __uint_as_float(sl & 0xffff0000u);
            float2 o;
            o.x = s0 * sigmoidf(acc[nt][2] + cc.x) + cr1*ll.x;
            o.y = s1 * sigmoidf(acc[nt][3] + cc.y) + cr1*ll.y;
            *(float2*)(hout + (size_t)m1*NU + n0) = o;
        }
    }
}

// ---------------- K5: h_tilde + after_preds + result ----------------
struct SM5 {
    float corr[TB][MS];
    float ht[TB][NU];
    float tp[TB][NU];
    float Ws[32][NU];
};

__global__ __launch_bounds__(256) void k5_out(const float* __restrict__ inp,
                                              const float* __restrict__ outW,
                                              const float* __restrict__ outb,
                                              float* __restrict__ out, int B){
    extern __shared__ char smraw[];
    SM5& S = *(SM5*)smraw;
    int t = threadIdx.x, rg = t>>5, cg = t&31;
    int b0 = blockIdx.x*TB;

    for(int i=t; i<TB*MS; i+=256){ int r=i>>6, m=i&63; S.corr[r][m] = inp[(size_t)(b0+r)*INC + NU + m]; }
    for(int i=t; i<TB*NU; i+=256){ int r=i>>7, c=i&127; S.tp[r][c] = inp[(size_t)(b0+r)*INC + NU + MS + c]; }
    __syncthreads();

    const float* hbase = out + (size_t)2*B;
    #pragma unroll 1
    for(int p=0; p<16; p++){
        int r = (t>>7) + p*2, c = t&127;
        const float* hb = hbase + (size_t)(b0+r)*MS*NU + c;
        float a0=0.f, a1=0.f;
        #pragma unroll
        for(int m=0; m<MS; m+=2){
            a0 = fmaf(S.corr[r][m+0], hb[(m+0)*NU], a0);
            a1 = fmaf(S.corr[r][m+1], hb[(m+1)*NU], a1);
        }
        S.ht[r][c] = a0 + a1;
    }

    float acc[4][4];
    #pragma unroll
    for(int i=0;i<4;i++){ acc[i][0]=acc[i][1]=acc[i][2]=acc[i][3]=0.f; }
    gemm_rt(S.ht, outW,         S.Ws, rg, cg, acc);
    gemm_rt(S.tp, outW + NU*NU, S.Ws, rg, cg, acc);

    float s[4];
    #pragma unroll
    for(int i=0;i<4;i++){
        s[i]=0.f;
        #pragma unroll
        for(int j=0;j<4;j++) s[i] += sigmoidf(acc[i][j] + outb[cg*4+j]);
    }
    #pragma unroll
    for(int off=16; off; off>>=1){
        #pragma unroll
        for(int i=0;i<4;i++) s[i] += __shfl_xor_sync(0xffffffffu, s[i], off);
    }
    if(cg==0){
        #pragma unroll
        for(int i=0;i<4;i++){
            int b = b0 + rg*4 + i;
            float p  = g_preds[b];
            float ap = s[i] * (1.f/NU);
            out[(size_t)b*2]     = p;
            out[(size_t)b*2 + 1] = (ap - p) / (1.f - p);
        }
    }
}

// ---------------- launch ----------------
extern "C" void kernel_launch(void* const* d_in, const int* in_sizes, int n_in,
                              void* d_out, int out_size){
    const float* inp    = (const float*)d_in[0];
    const float* states = (const float*)d_in[1];
    const float* tw     = (const float*)d_in[2];
    const float* aw     = (const float*)d_in[3];
    const float* hw     = (const float*)d_in[4];
    const float* Wf     = (const float*)d_in[5];
    const float* bias   = (const float*)d_in[6];
    const float* g3W    = (const float*)d_in[7];
    const float* g3b    = (const float*)d_in[8];
    const float* outW   = (const float*)d_in[9];
    const float* outb   = (const float*)d_in[10];
    const float* tgW    = (const float*)d_in[11];
    const float* tgb    = (const float*)d_in[12];
    const float* agW    = (const float*)d_in[13];
    const float* agb    = (const float*)d_in[14];
    const float* hgW    = (const float*)d_in[15];
    const float* hgb    = (const float*)d_in[16];
    float* out = (float*)d_out;
    int B = in_sizes[0] / INC;

    cudaFuncSetAttribute(k23,     cudaFuncAttributeMaxDynamicSharedMemorySize, (int)sizeof(SM23));
    cudaFuncSetAttribute(k4_main, cudaFuncAttributeMaxDynamicSharedMemorySize, SM4_TOTAL);
    cudaFuncSetAttribute(k5_out,  cudaFuncAttributeMaxDynamicSharedMemorySize, (int)sizeof(SM5));

    k0_wsum   <<<1, 128>>>(g3W);
    k0b_wsplit<<<64, 256>>>(g3W);
    k1_hpt    <<<B, 128>>>(inp, states);
    k23       <<<B/TB, 256, sizeof(SM23)>>>(inp, outW, outb, tgW, tgb, agW, agb, hgW, hgb,
                                            g3W, g3b, tw, aw, hw, Wf, bias);
    k4_main   <<<B, 128, SM4_TOTAL>>>(inp, states, out, B);
    k5_out    <<<B/TB, 256, sizeof(SM5)>>>(inp, outW, outb, out, B);
}

// round 6
// speedup vs baseline: 1.6287x; 1.2728x over previous
#include <cuda_runtime.h>
#include <cuda_bf16.h>
#include <cstdint>

#define NU   128
#define MS   64
#define INC  323          // [0:128) interact | [128:192) corr | [192:320) topic | 320 t | 321 a | 322 h
#define BMAX 4096
#define TB   32

// ---------------- scratch (device globals; no allocation) ----------------
__device__ float g_hpt  [BMAX*NU];
__device__ float g_lg   [BMAX*NU];
__device__ float g_c    [BMAX*NU];
__device__ float g_preds[BMAX];
__device__ float g_ws   [3*NU];
__device__ float g_gain [3*BMAX*NU];
__device__ float g_fdot [12ULL*BMAX*NU];
__device__ __nv_bfloat16 g_w1hi[NU*NU];
__device__ __nv_bfloat16 g_w1lo[NU*NU];

__device__ __forceinline__ float sigmoidf(float x){ return 1.f/(1.f+__expf(-x)); }

__device__ __forceinline__ int swzA(int row, int cb){ return row*256 + (cb ^ ((row&7)<<4)); }

#define MMA16816(c, a, b0v, b1v) \
    asm volatile("mma.sync.aligned.m16n8k16.row.col.f32.bf16.bf16.f32 " \
        "{%0,%1,%2,%3}, {%4,%5,%6,%7}, {%8,%9}, {%0,%1,%2,%3};" \
        : "+f"((c)[0]), "+f"((c)[1]), "+f"((c)[2]), "+f"((c)[3]) \
        : "r"((a)[0]), "r"((a)[1]), "r"((a)[2]), "r"((a)[3]), "r"(b0v), "r"(b1v))

// ---------------- K0: colsums of gate3_W factor rows ----------------
__global__ void k0_wsum(const float* __restrict__ g3W){
    int n = threadIdx.x;
    #pragma unroll
    for(int g=0; g<3; g++){
        float s = 0.f;
        for(int u=0; u<50; u++) s += g3W[(256 + g*50 + u)*NU + n];
        g_ws[g*NU + n] = s;
    }
}

// ---------------- K0b: split-transpose gate3_W[0:128] -> bf16 hi/lo, swizzled ----------------
__global__ __launch_bounds__(256) void k0b_wsplit(const float* __restrict__ g3W){
    int id = blockIdx.x*256 + threadIdx.x;
    int n = id >> 7, k = id & 127;
    float v = g3W[k*NU + n];
    __nv_bfloat16 hi = __float2bfloat16(v);
    __nv_bfloat16 lo = __float2bfloat16(v - __bfloat162float(hi));
    int off = swzA(n, 2*k);
    *(__nv_bfloat16*)((char*)g_w1hi + off) = hi;
    *(__nv_bfloat16*)((char*)g_w1lo + off) = lo;
}

// ---------------- K1: h_pre_tilde ----------------
__global__ __launch_bounds__(128) void k1_hpt(const float* __restrict__ inp,
                                              const float* __restrict__ states){
    int b = blockIdx.x, n = threadIdx.x;
    __shared__ float corr[MS];
    if(n < MS) corr[n] = inp[(size_t)b*INC + NU + n];
    __syncthreads();
    const float* hp = states + (size_t)b*MS*NU;
    float a0=0.f,a1=0.f,a2=0.f,a3=0.f;
    #pragma unroll
    for(int m=0; m<MS; m+=4){
        a0 = fmaf(corr[m+0], hp[(m+0)*NU + n], a0);
        a1 = fmaf(corr[m+1], hp[(m+1)*NU + n], a1);
        a2 = fmaf(corr[m+2], hp[(m+2)*NU + n], a2);
        a3 = fmaf(corr[m+3], hp[(m+3)*NU + n], a3);
    }
    g_hpt[b*NU + n] = (a0+a1)+(a2+a3);
}

// ================= register-tiled GEMM core =================
__device__ __forceinline__ void gemm_rt(const float (*A)[NU], const float* __restrict__ W,
                                        float (*Ws)[NU], int rg, int cg, float acc[4][4]){
    int t = threadIdx.x;
    #pragma unroll 1
    for(int kt=0; kt<4; kt++){
        __syncthreads();
        const float4* src = (const float4*)(W + kt*32*NU);
        float4* dst = (float4*)Ws;
        #pragma unroll
        for(int i=0;i<4;i++) dst[t + i*256] = src[t + i*256];
        __syncthreads();
        #pragma unroll
        for(int k=0; k<32; k+=4){
            float4 w0 = *(const float4*)&Ws[k+0][cg*4];
            float4 w1 = *(const float4*)&Ws[k+1][cg*4];
            float4 w2 = *(const float4*)&Ws[k+2][cg*4];
            float4 w3 = *(const float4*)&Ws[k+3][cg*4];
            #pragma unroll
            for(int i=0;i<4;i++){
                float4 a = *(const float4*)&A[rg*4+i][kt*32+k];
                acc[i][0]=fmaf(a.x,w0.x,fmaf(a.y,w1.x,fmaf(a.z,w2.x,fmaf(a.w,w3.x,acc[i][0]))));
                acc[i][1]=fmaf(a.x,w0.y,fmaf(a.y,w1.y,fmaf(a.z,w2.y,fmaf(a.w,w3.y,acc[i][1]))));
                acc[i][2]=fmaf(a.x,w0.z,fmaf(a.y,w1.z,fmaf(a.z,w2.z,fmaf(a.w,w3.z,acc[i][2]))));
                acc[i][3]=fmaf(a.x,w0.w,fmaf(a.y,w1.w,fmaf(a.z,w2.w,fmaf(a.w,w3.w,acc[i][3]))));
            }
        }
    }
}

// ---------------- K2a: slot 0=preds, 1..3=gates, 4=c ----------------
struct SM2A {
    float A0[TB][NU];
    float A1[TB][NU];
    float Ws[32][NU];
    float fact[TB][4];
};

__global__ __launch_bounds__(256) void k2a(const float* __restrict__ inp,
    const float* __restrict__ outW, const float* __restrict__ outb,
    const float* __restrict__ tgW,  const float* __restrict__ tgb,
    const float* __restrict__ agW,  const float* __restrict__ agb,
    const float* __restrict__ hgW,  const float* __restrict__ hgb,
    const float* __restrict__ g3W,  const float* __restrict__ g3b){

    extern __shared__ char smraw[];
    SM2A& S = *(SM2A*)smraw;
    int t = threadIdx.x, rg = t>>5, cg = t&31;
    int b0 = blockIdx.x*TB;
    int slot = blockIdx.y;

    for(int i=t; i<TB*NU; i+=256){
        int r = i>>7, c = i&127;
        S.A0[r][c] = g_hpt[(b0+r)*NU + c];
        S.A1[r][c] = (slot==0) ? inp[(size_t)(b0+r)*INC + NU + MS + c]   // topic
                               : inp[(size_t)(b0+r)*INC + c];            // interact
    }
    for(int i=t; i<TB*3; i+=256){ int r=i/3, g=i%3; S.fact[r][g] = inp[(size_t)(b0+r)*INC + 320 + g]; }

    float acc[4][4];
    #pragma unroll
    for(int i=0;i<4;i++){ acc[i][0]=acc[i][1]=acc[i][2]=acc[i][3]=0.f; }

    if(slot == 0){
        gemm_rt(S.A0, outW,         S.Ws, rg, cg, acc);
        gemm_rt(S.A1, outW + NU*NU, S.Ws, rg, cg, acc);
        float s[4];
        #pragma unroll
        for(int i=0;i<4;i++){
            s[i]=0.f;
            #pragma unroll
            for(int j=0;j<4;j++) s[i] += sigmoidf(acc[i][j] + outb[cg*4+j]);
        }
        #pragma unroll
        for(int off=16; off; off>>=1){
            #pragma unroll
            for(int i=0;i<4;i++) s[i] += __shfl_xor_sync(0xffffffffu, s[i], off);
        }
        if(cg==0){
            #pragma unroll
            for(int i=0;i<4;i++) g_preds[b0 + rg*4 + i] = s[i] * (1.f/NU);
        }
    } else if(slot <= 3){
        int g = slot - 1;
        const float* Wg = (g==0)? tgW : (g==1)? agW : hgW;
        const float* bg = (g==0)? tgb : (g==1)? agb : hgb;
        gemm_rt(S.A0, Wg,         S.Ws, rg, cg, acc);
        gemm_rt(S.A1, Wg + NU*NU, S.Ws, rg, cg, acc);
        #pragma unroll
        for(int i=0;i<4;i++){
            int b = b0 + rg*4 + i;
            float f = S.fact[rg*4+i][g];
            float gain = 0.3f + 0.7f*sigmoidf(10.f*(f - 0.3f));
            float4 o;
            o.x = sigmoidf((acc[i][0] + bg[cg*4+0]) * gain);
            o.y = sigmoidf((acc[i][1] + bg[cg*4+1]) * gain);
            o.z = sigmoidf((acc[i][2] + bg[cg*4+2]) * gain);
            o.w = sigmoidf((acc[i][3] + bg[cg*4+3]) * gain);
            *(float4*)&g_gain[(size_t)g*BMAX*NU + b*NU + cg*4] = o;
        }
    } else {
        gemm_rt(S.A1, g3W + NU*NU, S.Ws, rg, cg, acc);
        #pragma unroll
        for(int i=0;i<4;i++){
            int b = b0 + rg*4 + i;
            float f0=S.fact[rg*4+i][0], f1=S.fact[rg*4+i][1], f2=S.fact[rg*4+i][2];
            #pragma unroll
            for(int j=0;j<4;j++){
                int n = cg*4 + j;
                g_c[b*NU + n] = acc[i][j] + f0*g_ws[n] + f1*g_ws[NU+n] + f2*g_ws[2*NU+n] + g3b[n];
            }
        }
    }
}

// ---------------- K2b: fusion dot products (12 per batch-tile) ----------------
struct SM2B {
    float A[TB][NU];
    float Ws[32][NU];
};

__global__ __launch_bounds__(256) void k2b(const float* __restrict__ tw,
    const float* __restrict__ aw, const float* __restrict__ hw){
    extern __shared__ char smraw[];
    SM2B& S = *(SM2B*)smraw;
    int t = threadIdx.x, rg = t>>5, cg = t&31;
    int b0 = blockIdx.x*TB;
    int y = blockIdx.y;          // y = r*3 + g
    int r = y/3, g = y%3;
    const float* W = (g==0)? tw : (g==1)? aw : hw;

    for(int i=t; i<TB*NU; i+=256){
        int rr = i>>7, c = i&127;
        S.A[rr][c] = g_gain[(size_t)g*BMAX*NU + (b0+rr)*NU + c];
    }

    float acc[4][4];
    #pragma unroll
    for(int i=0;i<4;i++){ acc[i][0]=acc[i][1]=acc[i][2]=acc[i][3]=0.f; }
    gemm_rt(S.A, W + (size_t)r*129*NU, S.Ws, rg, cg, acc);

    const float* pad = W + ((size_t)r*129 + 128)*NU;
    float* dst = g_fdot + (size_t)y*BMAX*NU;
    #pragma unroll
    for(int i=0;i<4;i++){
        int b = b0 + rg*4 + i;
        float4 o;
        o.x = acc[i][0] + pad[cg*4+0];
        o.y = acc[i][1] + pad[cg*4+1];
        o.z = acc[i][2] + pad[cg*4+2];
        o.w = acc[i][3] + pad[cg*4+3];
        *(float4*)&dst[b*NU + cg*4] = o;
    }
}

// ---------------- K3c: combine -> learning_gain ----------------
__global__ __launch_bounds__(256) void k3c(const float* __restrict__ Wf,
                                           const float* __restrict__ bias, int B){
    int idx = blockIdx.x*256 + threadIdx.x;     // one float4 per thread
    size_t e = (size_t)idx*4;
    if(e >= (size_t)B*NU) return;
    int n = (int)(e & 127);
    float wf0=__ldg(Wf), wf1=__ldg(Wf+1), wf2=__ldg(Wf+2), wf3=__ldg(Wf+3);
    float4 bs = *(const float4*)&bias[n];
    float4 acc = make_float4(0.f,0.f,0.f,0.f);
    const float wfs[4] = {wf0, wf1, wf2, wf3};
    #pragma unroll
    for(int r=0; r<4; r++){
        float4 p0 = *(const float4*)&g_fdot[(size_t)(r*3+0)*BMAX*NU + e];
        float4 p1 = *(const float4*)&g_fdot[(size_t)(r*3+1)*BMAX*NU + e];
        float4 p2 = *(const float4*)&g_fdot[(size_t)(r*3+2)*BMAX*NU + e];
        acc.x = fmaf(wfs[r], p0.x*p1.x*p2.x, acc.x);
        acc.y = fmaf(wfs[r], p0.y*p1.y*p2.y, acc.y);
        acc.z = fmaf(wfs[r], p0.z*p1.z*p2.z, acc.z);
        acc.w = fmaf(wfs[r], p0.w*p1.w*p2.w, acc.w);
    }
    float4 o;
    o.x = fmaxf(acc.x + bs.x, 0.f);
    o.y = fmaxf(acc.y + bs.y, 0.f);
    o.z = fmaxf(acc.z + bs.z, 0.f);
    o.w = fmaxf(acc.w + bs.w, 0.f);
    *(float4*)&g_lg[e] = o;
}

// ---------------- K4: mma.sync forget-gate GEMM + fused state update ----------------
#define SM4_AHI 0
#define SM4_ALO 16384
#define SM4_WHI 32768
#define SM4_WLO 65536
#define SM4_AUX 98304
#define SM4_TOTAL (98304 + 1280)

__global__ __launch_bounds__(128)
void k4_main(const float* __restrict__ inp, const float* __restrict__ states,
             float* __restrict__ out, int B){
    extern __shared__ char sm[];
    float* corr_s = (float*)(sm + SM4_AUX);
    float* c_s    = (float*)(sm + SM4_AUX + 256);
    float* lg_s   = (float*)(sm + SM4_AUX + 768);

    int t = threadIdx.x, w = t>>5, l = t&31;
    int b = blockIdx.x;

    {
        const uint4* sh = (const uint4*)g_w1hi;
        const uint4* sl = (const uint4*)g_w1lo;
        uint4* dh = (uint4*)(sm + SM4_WHI);
        uint4* dl = (uint4*)(sm + SM4_WLO);
        for(int i=t; i<2048; i+=128){ dh[i]=sh[i]; dl[i]=sl[i]; }
    }
    {
        const float4* As = (const float4*)(states + (size_t)b*MS*NU);
        for(int f=t; f<2048; f+=128){
            int row = f>>5, cq = f&31;
            float4 v = As[f];
            __nv_bfloat16 h0=__float2bfloat16(v.x), h1=__float2bfloat16(v.y),
                          h2=__float2bfloat16(v.z), h3=__float2bfloat16(v.w);
            __nv_bfloat16 l0=__float2bfloat16(v.x-__bfloat162float(h0));
            __nv_bfloat16 l1=__float2bfloat16(v.y-__bfloat162float(h1));
            __nv_bfloat16 l2=__float2bfloat16(v.z-__bfloat162float(h2));
            __nv_bfloat16 l3=__float2bfloat16(v.w-__bfloat162float(h3));
            uint2 hv, lv;
            hv.x = (uint32_t)__bfloat16_as_ushort(h0) | ((uint32_t)__bfloat16_as_ushort(h1)<<16);
            hv.y = (uint32_t)__bfloat16_as_ushort(h2) | ((uint32_t)__bfloat16_as_ushort(h3)<<16);
            lv.x = (uint32_t)__bfloat16_as_ushort(l0) | ((uint32_t)__bfloat16_as_ushort(l1)<<16);
            lv.y = (uint32_t)__bfloat16_as_ushort(l2) | ((uint32_t)__bfloat16_as_ushort(l3)<<16);
            int off = swzA(row, cq*8);
            *(uint2*)(sm + SM4_AHI + off) = hv;
            *(uint2*)(sm + SM4_ALO + off) = lv;
        }
    }
    if(t < MS) corr_s[t] = inp[(size_t)b*INC + NU + t];
    if(t < NU){ c_s[t] = g_c[(size_t)b*NU + t]; lg_s[t] = g_lg[(size_t)b*NU + t]; }
    __syncthreads();

    int g = l>>2, tt = l&3;
    int r0 = w*16;
    float acc[16][4];
    #pragma unroll
    for(int nt=0; nt<16; nt++){ acc[nt][0]=acc[nt][1]=acc[nt][2]=acc[nt][3]=0.f; }

    #pragma unroll 1
    for(int kt=0; kt<8; kt++){
        int cb0 = kt*32 + tt*4, cb1 = cb0 + 16;
        uint32_t ah[4], al[4];
        ah[0] = *(const uint32_t*)(sm + SM4_AHI + swzA(r0+g,   cb0));
        ah[1] = *(const uint32_t*)(sm + SM4_AHI + swzA(r0+g+8, cb0));
        ah[2] = *(const uint32_t*)(sm + SM4_AHI + swzA(r0+g,   cb1));
        ah[3] = *(const uint32_t*)(sm + SM4_AHI + swzA(r0+g+8, cb1));
        al[0] = *(const uint32_t*)(sm + SM4_ALO + swzA(r0+g,   cb0));
        al[1] = *(const uint32_t*)(sm + SM4_ALO + swzA(r0+g+8, cb0));
        al[2] = *(const uint32_t*)(sm + SM4_ALO + swzA(r0+g,   cb1));
        al[3] = *(const uint32_t*)(sm + SM4_ALO + swzA(r0+g+8, cb1));
        #pragma unroll
        for(int nt=0; nt<16; nt++){
            uint32_t bh0 = *(const uint32_t*)(sm + SM4_WHI + swzA(nt*8+g, cb0));
            uint32_t bh1 = *(const uint32_t*)(sm + SM4_WHI + swzA(nt*8+g, cb1));
            uint32_t bl0 = *(const uint32_t*)(sm + SM4_WLO + swzA(nt*8+g, cb0));
            uint32_t bl1 = *(const uint32_t*)(sm + SM4_WLO + swzA(nt*8+g, cb1));
            MMA16816(acc[nt], ah, bh0, bh1);
            MMA16816(acc[nt], al, bh0, bh1);
            MMA16816(acc[nt], ah, bl0, bl1);
        }
    }

    float* hout = out + (size_t)2*B + (size_t)b*MS*NU;
    int m0 = r0 + g, m1 = r0 + g + 8;
    float cr0 = corr_s[m0], cr1 = corr_s[m1];
    #pragma unroll
    for(int nt=0; nt<16; nt++){
        int n0 = nt*8 + tt*2;
        float2 cc = *(const float2*)(c_s + n0);
        float2 ll = *(const float2*)(lg_s + n0);
        {
            uint32_t sh = *(const uint32_t*)(sm + SM4_AHI + swzA(m0, n0*2));
            uint32_t sl = *(const uint32_t*)(sm + SM4_ALO + swzA(m0, n0*2));
            float s0 = __uint_as_float(sh<<16) + __uint_as_float(sl<<16);
            float s1 = __uint_as_float(sh & 0xffff0000u) + __uint_as_float(sl & 0xffff0000u);
            float2 o;
            o.x = s0 * sigmoidf(acc[nt][0] + cc.x) + cr0*ll.x;
            o.y = s1 * sigmoidf(acc[nt][1] + cc.y) + cr0*ll.y;
            *(float2*)(hout + (size_t)m0*NU + n0) = o;
        }
        {
            uint32_t sh = *(const uint32_t*)(sm + SM4_AHI + swzA(m1, n0*2));
            uint32_t sl = *(const uint32_t*)(sm + SM4_ALO + swzA(m1, n0*2));
            float s0 = __uint_as_float(sh<<16) + __uint_as_float(sl<<16);
            float s1 = __uint_as_float(sh & 0xffff0000u) + __uint_as_float(sl & 0xffff0000u);
            float2 o;
            o.x = s0 * sigmoidf(acc[nt][2] + cc.x) + cr1*ll.x;
            o.y = s1 * sigmoidf(acc[nt][3] + cc.y) + cr1*ll.y;
            *(float2*)(hout + (size_t)m1*NU + n0) = o;
        }
    }
}

// ---------------- K5: h_tilde + after_preds + result ----------------
struct SM5 {
    float corr[TB][MS];
    float ht[TB][NU];
    float tp[TB][NU];
    float Ws[32][NU];
};

__global__ __launch_bounds__(256) void k5_out(const float* __restrict__ inp,
                                              const float* __restrict__ outW,
                                              const float* __restrict__ outb,
                                              float* __restrict__ out, int B){
    extern __shared__ char smraw[];
    SM5& S = *(SM5*)smraw;
    int t = threadIdx.x, rg = t>>5, cg = t&31;
    int b0 = blockIdx.x*TB;

    for(int i=t; i<TB*MS; i+=256){ int r=i>>6, m=i&63; S.corr[r][m] = inp[(size_t)(b0+r)*INC + NU + m]; }
    for(int i=t; i<TB*NU; i+=256){ int r=i>>7, c=i&127; S.tp[r][c] = inp[(size_t)(b0+r)*INC + NU + MS + c]; }
    __syncthreads();

    const float* hbase = out + (size_t)2*B;
    #pragma unroll 1
    for(int p=0; p<16; p++){
        int r = (t>>7) + p*2, c = t&127;
        const float* hb = hbase + (size_t)(b0+r)*MS*NU + c;
        float a0=0.f, a1=0.f;
        #pragma unroll
        for(int m=0; m<MS; m+=2){
            a0 = fmaf(S.corr[r][m+0], hb[(m+0)*NU], a0);
            a1 = fmaf(S.corr[r][m+1], hb[(m+1)*NU], a1);
        }
        S.ht[r][c] = a0 + a1;
    }

    float acc[4][4];
    #pragma unroll
    for(int i=0;i<4;i++){ acc[i][0]=acc[i][1]=acc[i][2]=acc[i][3]=0.f; }
    gemm_rt(S.ht, outW,         S.Ws, rg, cg, acc);
    gemm_rt(S.tp, outW + NU*NU, S.Ws, rg, cg, acc);

    float s[4];
    #pragma unroll
    for(int i=0;i<4;i++){
        s[i]=0.f;
        #pragma unroll
        for(int j=0;j<4;j++) s[i] += sigmoidf(acc[i][j] + outb[cg*4+j]);
    }
    #pragma unroll
    for(int off=16; off; off>>=1){
        #pragma unroll
        for(int i=0;i<4;i++) s[i] += __shfl_xor_sync(0xffffffffu, s[i], off);
    }
    if(cg==0){
        #pragma unroll
        for(int i=0;i<4;i++){
            int b = b0 + rg*4 + i;
            float p  = g_preds[b];
            float ap = s[i] * (1.f/NU);
            out[(size_t)b*2]     = p;
            out[(size_t)b*2 + 1] = (ap - p) / (1.f - p);
        }
    }
}

// ---------------- launch ----------------
extern "C" void kernel_launch(void* const* d_in, const int* in_sizes, int n_in,
                              void* d_out, int out_size){
    const float* inp    = (const float*)d_in[0];
    const float* states = (const float*)d_in[1];
    const float* tw     = (const float*)d_in[2];
    const float* aw     = (const float*)d_in[3];
    const float* hw     = (const float*)d_in[4];
    const float* Wf     = (const float*)d_in[5];
    const float* bias   = (const float*)d_in[6];
    const float* g3W    = (const float*)d_in[7];
    const float* g3b    = (const float*)d_in[8];
    const float* outW   = (const float*)d_in[9];
    const float* outb   = (const float*)d_in[10];
    const float* tgW    = (const float*)d_in[11];
    const float* tgb    = (const float*)d_in[12];
    const float* agW    = (const float*)d_in[13];
    const float* agb    = (const float*)d_in[14];
    const float* hgW    = (const float*)d_in[15];
    const float* hgb    = (const float*)d_in[16];
    float* out = (float*)d_out;
    int B = in_sizes[0] / INC;

    cudaFuncSetAttribute(k2a,     cudaFuncAttributeMaxDynamicSharedMemorySize, (int)sizeof(SM2A));
    cudaFuncSetAttribute(k2b,     cudaFuncAttributeMaxDynamicSharedMemorySize, (int)sizeof(SM2B));
    cudaFuncSetAttribute(k4_main, cudaFuncAttributeMaxDynamicSharedMemorySize, SM4_TOTAL);
    cudaFuncSetAttribute(k5_out,  cudaFuncAttributeMaxDynamicSharedMemorySize, (int)sizeof(SM5));

    k0_wsum   <<<1, 128>>>(g3W);
    k0b_wsplit<<<64, 256>>>(g3W);
    k1_hpt    <<<B, 128>>>(inp, states);
    {
        dim3 g2a(B/TB, 5);
        k2a<<<g2a, 256, sizeof(SM2A)>>>(inp, outW, outb, tgW, tgb, agW, agb, hgW, hgb, g3W, g3b);
    }
    {
        dim3 g2b(B/TB, 12);
        k2b<<<g2b, 256, sizeof(SM2B)>>>(tw, aw, hw);
    }
    k3c      <<<(B*NU/4 + 255)/256, 256>>>(Wf, bias, B);
    k4_main  <<<B, 128, SM4_TOTAL>>>(inp, states, out, B);
    k5_out   <<<B/TB, 256, sizeof(SM5)>>>(inp, outW, outb, out, B);
}

// round 8
// speedup vs baseline: 2.5695x; 1.5776x over previous
#include <cuda_runtime.h>
#include <cuda_bf16.h>
#include <cstdint>

#define NU   128
#define MS   64
#define INC  323          // [0:128) interact | [128:192) corr | [192:320) topic | 320 t | 321 a | 322 h
#define BMAX 4096
#define TB   32

// ---------------- scratch (device globals; no allocation) ----------------
__device__ float g_hpt   [BMAX*NU];
__device__ float g_lg    [BMAX*NU];
__device__ float g_c     [BMAX*NU];
__device__ float g_preds [BMAX];
__device__ float g_htilde[BMAX*NU];
__device__ float g_ws    [3*NU];
__device__ float g_gain  [3*BMAX*NU];
__device__ float g_fdot  [12ULL*BMAX*NU];
__device__ __nv_bfloat16 g_w1hi[NU*NU];
__device__ __nv_bfloat16 g_w1lo[NU*NU];

__device__ __forceinline__ float sigmoidf(float x){ return 1.f/(1.f+__expf(-x)); }
__device__ __forceinline__ int swzA(int row, int cb){ return row*256 + (cb ^ ((row&7)<<4)); }
__device__ __forceinline__ uint32_t bfu(__nv_bfloat16 h){ return (uint32_t)__bfloat16_as_ushort(h); }

#define MMA16816(c, a, b0v, b1v) \
    asm volatile("mma.sync.aligned.m16n8k16.row.col.f32.bf16.bf16.f32 " \
        "{%0,%1,%2,%3}, {%4,%5,%6,%7}, {%8,%9}, {%0,%1,%2,%3};" \
        : "+f"((c)[0]), "+f"((c)[1]), "+f"((c)[2]), "+f"((c)[3]) \
        : "r"((a)[0]), "r"((a)[1]), "r"((a)[2]), "r"((a)[3]), "r"(b0v), "r"(b1v))

// ---------------- K0: colsums of gate3_W factor rows ----------------
__global__ void k0_wsum(const float* __restrict__ g3W){
    int n = threadIdx.x;
    #pragma unroll
    for(int g=0; g<3; g++){
        float s = 0.f;
        for(int u=0; u<50; u++) s += g3W[(256 + g*50 + u)*NU + n];
        g_ws[g*NU + n] = s;
    }
}

// ---------------- K0b: split-transpose gate3_W[0:128] -> bf16 hi/lo, swizzled ----------------
__global__ __launch_bounds__(256) void k0b_wsplit(const float* __restrict__ g3W){
    int id = blockIdx.x*256 + threadIdx.x;
    int n = id >> 7, k = id & 127;
    float v = g3W[k*NU + n];
    __nv_bfloat16 hi = __float2bfloat16(v);
    __nv_bfloat16 lo = __float2bfloat16(v - __bfloat162float(hi));
    int off = swzA(n, 2*k);
    *(__nv_bfloat16*)((char*)g_w1hi + off) = hi;
    *(__nv_bfloat16*)((char*)g_w1lo + off) = lo;
}

// ---------------- K1: h_pre_tilde ----------------
__global__ __launch_bounds__(128) void k1_hpt(const float* __restrict__ inp,
                                              const float* __restrict__ states){
    int b = blockIdx.x, n = threadIdx.x;
    __shared__ float corr[MS];
    if(n < MS) corr[n] = inp[(size_t)b*INC + NU + n];
    __syncthreads();
    const float* hp = states + (size_t)b*MS*NU;
    float a0=0.f,a1=0.f,a2=0.f,a3=0.f;
    #pragma unroll
    for(int m=0; m<MS; m+=4){
        a0 = fmaf(corr[m+0], hp[(m+0)*NU + n], a0);
        a1 = fmaf(corr[m+1], hp[(m+1)*NU + n], a1);
        a2 = fmaf(corr[m+2], hp[(m+2)*NU + n], a2);
        a3 = fmaf(corr[m+3], hp[(m+3)*NU + n], a3);
    }
    g_hpt[b*NU + n] = (a0+a1)+(a2+a3);
}

// ================= register-tiled GEMM core =================
__device__ __forceinline__ void gemm_rt(const float (*A)[NU], const float* __restrict__ W,
                                        float (*Ws)[NU], int rg, int cg, float acc[4][4]){
    int t = threadIdx.x;
    #pragma unroll 1
    for(int kt=0; kt<4; kt++){
        __syncthreads();
        const float4* src = (const float4*)(W + kt*32*NU);
        float4* dst = (float4*)Ws;
        #pragma unroll
        for(int i=0;i<4;i++) dst[t + i*256] = src[t + i*256];
        __syncthreads();
        #pragma unroll
        for(int k=0; k<32; k+=4){
            float4 w0 = *(const float4*)&Ws[k+0][cg*4];
            float4 w1 = *(const float4*)&Ws[k+1][cg*4];
            float4 w2 = *(const float4*)&Ws[k+2][cg*4];
            float4 w3 = *(const float4*)&Ws[k+3][cg*4];
            #pragma unroll
            for(int i=0;i<4;i++){
                float4 a = *(const float4*)&A[rg*4+i][kt*32+k];
                acc[i][0]=fmaf(a.x,w0.x,fmaf(a.y,w1.x,fmaf(a.z,w2.x,fmaf(a.w,w3.x,acc[i][0]))));
                acc[i][1]=fmaf(a.x,w0.y,fmaf(a.y,w1.y,fmaf(a.z,w2.y,fmaf(a.w,w3.y,acc[i][1]))));
                acc[i][2]=fmaf(a.x,w0.z,fmaf(a.y,w1.z,fmaf(a.z,w2.z,fmaf(a.w,w3.z,acc[i][2]))));
                acc[i][3]=fmaf(a.x,w0.w,fmaf(a.y,w1.w,fmaf(a.z,w2.w,fmaf(a.w,w3.w,acc[i][3]))));
            }
        }
    }
}

// ---------------- K2a: slot 0=preds, 1..3=gates, 4=c ----------------
struct SM2A {
    float A0[TB][NU];
    float A1[TB][NU];
    float Ws[32][NU];
    float fact[TB][4];
};

__global__ __launch_bounds__(256) void k2a(const float* __restrict__ inp,
    const float* __restrict__ outW, const float* __restrict__ outb,
    const float* __restrict__ tgW,  const float* __restrict__ tgb,
    const float* __restrict__ agW,  const float* __restrict__ agb,
    const float* __restrict__ hgW,  const float* __restrict__ hgb,
    const float* __restrict__ g3W,  const float* __restrict__ g3b){

    extern __shared__ char smraw[];
    SM2A& S = *(SM2A*)smraw;
    int t = threadIdx.x, rg = t>>5, cg = t&31;
    int b0 = blockIdx.x*TB;
    int slot = blockIdx.y;

    for(int i=t; i<TB*NU; i+=256){
        int r = i>>7, c = i&127;
        S.A0[r][c] = g_hpt[(b0+r)*NU + c];
        S.A1[r][c] = (slot==0) ? inp[(size_t)(b0+r)*INC + NU + MS + c]
                               : inp[(size_t)(b0+r)*INC + c];
    }
    for(int i=t; i<TB*3; i+=256){ int r=i/3, g=i%3; S.fact[r][g] = inp[(size_t)(b0+r)*INC + 320 + g]; }

    float acc[4][4];
    #pragma unroll
    for(int i=0;i<4;i++){ acc[i][0]=acc[i][1]=acc[i][2]=acc[i][3]=0.f; }

    if(slot == 0){
        gemm_rt(S.A0, outW,         S.Ws, rg, cg, acc);
        gemm_rt(S.A1, outW + NU*NU, S.Ws, rg, cg, acc);
        float s[4];
        #pragma unroll
        for(int i=0;i<4;i++){
            s[i]=0.f;
            #pragma unroll
            for(int j=0;j<4;j++) s[i] += sigmoidf(acc[i][j] + outb[cg*4+j]);
        }
        #pragma unroll
        for(int off=16; off; off>>=1){
            #pragma unroll
            for(int i=0;i<4;i++) s[i] += __shfl_xor_sync(0xffffffffu, s[i], off);
        }
        if(cg==0){
            #pragma unroll
            for(int i=0;i<4;i++) g_preds[b0 + rg*4 + i] = s[i] * (1.f/NU);
        }
    } else if(slot <= 3){
        int g = slot - 1;
        const float* Wg = (g==0)? tgW : (g==1)? agW : hgW;
        const float* bg = (g==0)? tgb : (g==1)? agb : hgb;
        gemm_rt(S.A0, Wg,         S.Ws, rg, cg, acc);
        gemm_rt(S.A1, Wg + NU*NU, S.Ws, rg, cg, acc);
        #pragma unroll
        for(int i=0;i<4;i++){
            int b = b0 + rg*4 + i;
            float f = S.fact[rg*4+i][g];
            float gain = 0.3f + 0.7f*sigmoidf(10.f*(f - 0.3f));
            float4 o;
            o.x = sigmoidf((acc[i][0] + bg[cg*4+0]) * gain);
            o.y = sigmoidf((acc[i][1] + bg[cg*4+1]) * gain);
            o.z = sigmoidf((acc[i][2] + bg[cg*4+2]) * gain);
            o.w = sigmoidf((acc[i][3] + bg[cg*4+3]) * gain);
            *(float4*)&g_gain[(size_t)g*BMAX*NU + b*NU + cg*4] = o;
        }
    } else {
        gemm_rt(S.A1, g3W + NU*NU, S.Ws, rg, cg, acc);
        #pragma unroll
        for(int i=0;i<4;i++){
            int b = b0 + rg*4 + i;
            float f0=S.fact[rg*4+i][0], f1=S.fact[rg*4+i][1], f2=S.fact[rg*4+i][2];
            #pragma unroll
            for(int j=0;j<4;j++){
                int n = cg*4 + j;
                g_c[b*NU + n] = acc[i][j] + f0*g_ws[n] + f1*g_ws[NU+n] + f2*g_ws[2*NU+n] + g3b[n];
            }
        }
    }
}

// ---------------- K2b: fusion dot products ----------------
struct SM2B {
    float A[TB][NU];
    float Ws[32][NU];
};

__global__ __launch_bounds__(256) void k2b(const float* __restrict__ tw,
    const float* __restrict__ aw, const float* __restrict__ hw){
    extern __shared__ char smraw[];
    SM2B& S = *(SM2B*)smraw;
    int t = threadIdx.x, rg = t>>5, cg = t&31;
    int b0 = blockIdx.x*TB;
    int y = blockIdx.y;
    int r = y/3, g = y%3;
    const float* W = (g==0)? tw : (g==1)? aw : hw;

    for(int i=t; i<TB*NU; i+=256){
        int rr = i>>7, c = i&127;
        S.A[rr][c] = g_gain[(size_t)g*BMAX*NU + (b0+rr)*NU + c];
    }

    float acc[4][4];
    #pragma unroll
    for(int i=0;i<4;i++){ acc[i][0]=acc[i][1]=acc[i][2]=acc[i][3]=0.f; }
    gemm_rt(S.A, W + (size_t)r*129*NU, S.Ws, rg, cg, acc);

    const float* pad = W + ((size_t)r*129 + 128)*NU;
    float* dst = g_fdot + (size_t)y*BMAX*NU;
    #pragma unroll
    for(int i=0;i<4;i++){
        int b = b0 + rg*4 + i;
        float4 o;
        o.x = acc[i][0] + pad[cg*4+0];
        o.y = acc[i][1] + pad[cg*4+1];
        o.z = acc[i][2] + pad[cg*4+2];
        o.w = acc[i][3] + pad[cg*4+3];
        *(float4*)&dst[b*NU + cg*4] = o;
    }
}

// ---------------- K3c: combine -> learning_gain ----------------
__global__ __launch_bounds__(256) void k3c(const float* __restrict__ Wf,
                                           const float* __restrict__ bias, int B){
    int idx = blockIdx.x*256 + threadIdx.x;
    size_t e = (size_t)idx*4;
    if(e >= (size_t)B*NU) return;
    int n = (int)(e & 127);
    float wfs[4] = {__ldg(Wf), __ldg(Wf+1), __ldg(Wf+2), __ldg(Wf+3)};
    float4 bs = *(const float4*)&bias[n];
    float4 acc = make_float4(0.f,0.f,0.f,0.f);
    #pragma unroll
    for(int r=0; r<4; r++){
        float4 p0 = *(const float4*)&g_fdot[(size_t)(r*3+0)*BMAX*NU + e];
        float4 p1 = *(const float4*)&g_fdot[(size_t)(r*3+1)*BMAX*NU + e];
        float4 p2 = *(const float4*)&g_fdot[(size_t)(r*3+2)*BMAX*NU + e];
        acc.x = fmaf(wfs[r], p0.x*p1.x*p2.x, acc.x);
        acc.y = fmaf(wfs[r], p0.y*p1.y*p2.y, acc.y);
        acc.z = fmaf(wfs[r], p0.z*p1.z*p2.z, acc.z);
        acc.w = fmaf(wfs[r], p0.w*p1.w*p2.w, acc.w);
    }
    float4 o;
    o.x = fmaxf(acc.x + bs.x, 0.f);
    o.y = fmaxf(acc.y + bs.y, 0.f);
    o.z = fmaxf(acc.z + bs.z, 0.f);
    o.w = fmaxf(acc.w + bs.w, 0.f);
    *(float4*)&g_lg[e] = o;
}

// ---------------- K4 v2: mma.sync GEMM (A from global) + state update + h_tilde ----------------
// One CTA = 2 batches (M=128 rows), 256 threads / 8 warps. W hi/lo in smem only.
#define SM4_WHI 0
#define SM4_WLO 32768
#define SM4_HTW 65536                     // 8*128 floats
#define SM4_AUX (65536 + 4096)
#define SM4_TOTAL (SM4_AUX + 2560)

__global__ __launch_bounds__(256, 2)
void k4_main(const float* __restrict__ inp, const float* __restrict__ states,
             float* __restrict__ out, int B){
    extern __shared__ char sm[];
    float* htw    = (float*)(sm + SM4_HTW);
    float* corr_s = (float*)(sm + SM4_AUX);
    float* c_s    = (float*)(sm + SM4_AUX + 512);
    float* lg_s   = (float*)(sm + SM4_AUX + 1536);

    int t = threadIdx.x, w = t>>5, l = t&31;
    int g = l>>2, tt = l&3;
    int bb = blockIdx.x;                  // batches 2bb, 2bb+1
    size_t row0 = (size_t)bb*128;

    // stage W hi/lo
    {
        const uint4* shv = (const uint4*)g_w1hi;
        const uint4* slv = (const uint4*)g_w1lo;
        uint4* dh = (uint4*)(sm + SM4_WHI);
        uint4* dl = (uint4*)(sm + SM4_WLO);
        for(int i=t; i<2048; i+=256){ dh[i]=shv[i]; dl[i]=slv[i]; }
    }
    if(t < 128) corr_s[t] = inp[(size_t)(2*bb + (t>>6))*INC + NU + (t&63)];
    c_s[t]  = g_c [(size_t)2*bb*NU + t];
    lg_s[t] = g_lg[(size_t)2*bb*NU + t];

    int r0 = w*16;
    const float* a00 = states + (row0 + r0 + g    )*NU;
    const float* a01 = states + (row0 + r0 + g + 8)*NU;

    float acc[16][4];
    #pragma unroll
    for(int nt=0; nt<16; nt++){ acc[nt][0]=acc[nt][1]=acc[nt][2]=acc[nt][3]=0.f; }

    __syncthreads();

    // software-pipelined mainloop over K (8 chunks of 16)
    float2 av0[4], av1[4];
    {
        int c0 = tt*2;
        av0[0] = *(const float2*)(a00 + c0);
        av0[1] = *(const float2*)(a01 + c0);
        av0[2] = *(const float2*)(a00 + c0 + 8);
        av0[3] = *(const float2*)(a01 + c0 + 8);
    }
    #pragma unroll
    for(int kt=0; kt<8; kt++){
        if(kt < 7){
            int c0 = (kt+1)*16 + tt*2;
            av1[0] = *(const float2*)(a00 + c0);
            av1[1] = *(const float2*)(a01 + c0);
            av1[2] = *(const float2*)(a00 + c0 + 8);
            av1[3] = *(const float2*)(a01 + c0 + 8);
        }
        uint32_t ah[4], al[4];
        #pragma unroll
        for(int i=0;i<4;i++){
            float x = av0[i].x, y = av0[i].y;
            __nv_bfloat16 hx = __float2bfloat16(x), hy = __float2bfloat16(y);
            ah[i] = bfu(hx) | (bfu(hy)<<16);
            al[i] = bfu(__float2bfloat16(x - __bfloat162float(hx)))
                  | (bfu(__float2bfloat16(y - __bfloat162float(hy)))<<16);
        }
        int cb0 = kt*32 + tt*4, cb1 = cb0 + 16;
        #pragma unroll
        for(int nt=0; nt<16; nt++){
            uint32_t bh0 = *(const uint32_t*)(sm + SM4_WHI + swzA(nt*8+g, cb0));
            uint32_t bh1 = *(const uint32_t*)(sm + SM4_WHI + swzA(nt*8+g, cb1));
            uint32_t bl0 = *(const uint32_t*)(sm + SM4_WLO + swzA(nt*8+g, cb0));
            uint32_t bl1 = *(const uint32_t*)(sm + SM4_WLO + swzA(nt*8+g, cb1));
            MMA16816(acc[nt], ah, bh0, bh1);
            MMA16816(acc[nt], al, bh0, bh1);
            MMA16816(acc[nt], ah, bl0, bl1);
        }
        #pragma unroll
        for(int i=0;i<4;i++) av0[i] = av1[i];
    }

    // epilogue: forget gate + state update + h_tilde partials
    int m0 = r0 + g, m1 = r0 + g + 8;     // same batch (m0,m1 in same 64-block)
    int boff = (m0 >> 6) * NU;
    float cr0 = corr_s[m0], cr1 = corr_s[m1];
    float* h0 = out + (size_t)2*B + (row0 + m0)*NU;
    float* h1 = out + (size_t)2*B + (row0 + m1)*NU;

    #pragma unroll
    for(int nt=0; nt<16; nt++){
        int n0 = nt*8 + tt*2;
        float2 a0v = *(const float2*)(a00 + n0);
        float2 a1v = *(const float2*)(a01 + n0);
        float2 cc  = *(const float2*)(c_s  + boff + n0);
        float2 ll  = *(const float2*)(lg_s + boff + n0);
        float2 o0, o1;
        o0.x = a0v.x * sigmoidf(acc[nt][0] + cc.x) + cr0*ll.x;
        o0.y = a0v.y * sigmoidf(acc[nt][1] + cc.y) + cr0*ll.y;
        o1.x = a1v.x * sigmoidf(acc[nt][2] + cc.x) + cr1*ll.x;
        o1.y = a1v.y * sigmoidf(acc[nt][3] + cc.y) + cr1*ll.y;
        *(float2*)(h0 + n0) = o0;
        *(float2*)(h1 + n0) = o1;
        // h_tilde partial for cols n0, n0+1 from rows m0, m1
        float px = fmaf(cr0, o0.x, cr1*o1.x);
        float py = fmaf(cr0, o0.y, cr1*o1.y);
        // reduce over g (lane bits [4:2])
        px += __shfl_xor_sync(0xffffffffu, px, 4);
        py += __shfl_xor_sync(0xffffffffu, py, 4);
        px += __shfl_xor_sync(0xffffffffu, px, 8);
        py += __shfl_xor_sync(0xffffffffu, py, 8);
        px += __shfl_xor_sync(0xffffffffu, px, 16);
        py += __shfl_xor_sync(0xffffffffu, py, 16);
        if(g == 0){ htw[w*NU + n0] = px; htw[w*NU + n0 + 1] = py; }
    }
    __syncthreads();
    {
        int batch = t>>7, col = t&127;
        float s = htw[(batch*4+0)*NU + col] + htw[(batch*4+1)*NU + col]
                + htw[(batch*4+2)*NU + col] + htw[(batch*4+3)*NU + col];
        g_htilde[(size_t)(2*bb + batch)*NU + col] = s;
    }
}

// ---------------- K5 v2: after_preds from g_htilde + result ----------------
struct SM5 {
    float A0[TB][NU];
    float A1[TB][NU];
    float Ws[32][NU];
};

__global__ __launch_bounds__(256) void k5_out(const float* __restrict__ inp,
                                              const float* __restrict__ outW,
                                              const float* __restrict__ outb,
                                              float* __restrict__ out, int B){
    extern __shared__ char smraw[];
    SM5& S = *(SM5*)smraw;
    int t = threadIdx.x, rg = t>>5, cg = t&31;
    int b0 = blockIdx.x*TB;

    for(int i=t; i<TB*NU; i+=256){
        int r = i>>7, c = i&127;
        S.A0[r][c] = g_htilde[(size_t)(b0+r)*NU + c];
        S.A1[r][c] = inp[(size_t)(b0+r)*INC + NU + MS + c];
    }

    float acc[4][4];
    #pragma unroll
    for(int i=0;i<4;i++){ acc[i][0]=acc[i][1]=acc[i][2]=acc[i][3]=0.f; }
    gemm_rt(S.A0, outW,         S.Ws, rg, cg, acc);
    gemm_rt(S.A1, outW + NU*NU, S.Ws, rg, cg, acc);

    float s[4];
    #pragma unroll
    for(int i=0;i<4;i++){
        s[i]=0.f;
        #pragma unroll
        for(int j=0;j<4;j++) s[i] += sigmoidf(acc[i][j] + outb[cg*4+j]);
    }
    #pragma unroll
    for(int off=16; off; off>>=1){
        #pragma unroll
        for(int i=0;i<4;i++) s[i] += __shfl_xor_sync(0xffffffffu, s[i], off);
    }
    if(cg==0){
        #pragma unroll
        for(int i=0;i<4;i++){
            int b = b0 + rg*4 + i;
            float p  = g_preds[b];
            float ap = s[i] * (1.f/NU);
            out[(size_t)b*2]     = p;
            out[(size_t)b*2 + 1] = (ap - p) / (1.f - p);
        }
    }
}

// ---------------- launch ----------------
extern "C" void kernel_launch(void* const* d_in, const int* in_sizes, int n_in,
                              void* d_out, int out_size){
    const float* inp    = (const float*)d_in[0];
    const float* states = (const float*)d_in[1];
    const float* tw     = (const float*)d_in[2];
    const float* aw     = (const float*)d_in[3];
    const float* hw     = (const float*)d_in[4];
    const float* Wf     = (const float*)d_in[5];
    const float* bias   = (const float*)d_in[6];
    const float* g3W    = (const float*)d_in[7];
    const float* g3b    = (const float*)d_in[8];
    const float* outW   = (const float*)d_in[9];
    const float* outb   = (const float*)d_in[10];
    const float* tgW    = (const float*)d_in[11];
    const float* tgb    = (const float*)d_in[12];
    const float* agW    = (const float*)d_in[13];
    const float* agb    = (const float*)d_in[14];
    const float* hgW    = (const float*)d_in[15];
    const float* hgb    = (const float*)d_in[16];
    float* out = (float*)d_out;
    int B = in_sizes[0] / INC;

    cudaFuncSetAttribute(k2a,     cudaFuncAttributeMaxDynamicSharedMemorySize, (int)sizeof(SM2A));
    cudaFuncSetAttribute(k2b,     cudaFuncAttributeMaxDynamicSharedMemorySize, (int)sizeof(SM2B));
    cudaFuncSetAttribute(k4_main, cudaFuncAttributeMaxDynamicSharedMemorySize, SM4_TOTAL);
    cudaFuncSetAttribute(k5_out,  cudaFuncAttributeMaxDynamicSharedMemorySize, (int)sizeof(SM5));

    k0_wsum   <<<1, 128>>>(g3W);
    k0b_wsplit<<<64, 256>>>(g3W);
    k1_hpt    <<<B, 128>>>(inp, states);
    {
        dim3 g2a(B/TB, 5);
        k2a<<<g2a, 256, sizeof(SM2A)>>>(inp, outW, outb, tgW, tgb, agW, agb, hgW, hgb, g3W, g3b);
    }
    {
        dim3 g2b(B/TB, 12);
        k2b<<<g2b, 256, sizeof(SM2B)>>>(tw, aw, hw);
    }
    k3c      <<<(B*NU/4 + 255)/256, 256>>>(Wf, bias, B);
    k4_main  <<<B/2, 256, SM4_TOTAL>>>(inp, states, out, B);
    k5_out   <<<B/TB, 256, sizeof(SM5)>>>(inp, outW, outb, out, B);
}

// round 9
// speedup vs baseline: 2.5822x; 1.0050x over previous
#include <cuda_runtime.h>
#include <cuda_bf16.h>
#include <cstdint>

#define NU   128
#define MS   64
#define INC  323          // [0:128) interact | [128:192) corr | [192:320) topic | 320 t | 321 a | 322 h
#define BMAX 4096
#define TB   32

// ---------------- scratch (device globals; no allocation) ----------------
__device__ float g_hpt   [BMAX*NU];
__device__ float g_lg    [BMAX*NU];
__device__ float g_c     [BMAX*NU];
__device__ float g_preds [BMAX];
__device__ float g_htilde[BMAX*NU];
__device__ float g_ws    [3*NU];
__device__ float g_gain  [3*BMAX*NU];
__device__ float g_fdot  [12ULL*BMAX*NU];
__device__ __nv_bfloat16 g_w1hi[NU*NU];
__device__ __nv_bfloat16 g_w1lo[NU*NU];

__device__ __forceinline__ float sigmoidf(float x){ return 1.f/(1.f+__expf(-x)); }
__device__ __forceinline__ int swzA(int row, int cb){ return row*256 + (cb ^ ((row&7)<<4)); }
__device__ __forceinline__ uint32_t bfu(__nv_bfloat16 h){ return (uint32_t)__bfloat16_as_ushort(h); }

#define MMA16816(c, a, b0v, b1v) \
    asm volatile("mma.sync.aligned.m16n8k16.row.col.f32.bf16.bf16.f32 " \
        "{%0,%1,%2,%3}, {%4,%5,%6,%7}, {%8,%9}, {%0,%1,%2,%3};" \
        : "+f"((c)[0]), "+f"((c)[1]), "+f"((c)[2]), "+f"((c)[3]) \
        : "r"((a)[0]), "r"((a)[1]), "r"((a)[2]), "r"((a)[3]), "r"(b0v), "r"(b1v))

// ---------------- K0: colsums of gate3_W factor rows ----------------
__global__ void k0_wsum(const float* __restrict__ g3W){
    int n = threadIdx.x;
    #pragma unroll
    for(int g=0; g<3; g++){
        float s = 0.f;
        for(int u=0; u<50; u++) s += g3W[(256 + g*50 + u)*NU + n];
        g_ws[g*NU + n] = s;
    }
}

// ---------------- K0b: split-transpose gate3_W[0:128] -> bf16 hi/lo, swizzled ----------------
__global__ __launch_bounds__(256) void k0b_wsplit(const float* __restrict__ g3W){
    int id = blockIdx.x*256 + threadIdx.x;
    int n = id >> 7, k = id & 127;
    float v = g3W[k*NU + n];
    __nv_bfloat16 hi = __float2bfloat16(v);
    __nv_bfloat16 lo = __float2bfloat16(v - __bfloat162float(hi));
    int off = swzA(n, 2*k);
    *(__nv_bfloat16*)((char*)g_w1hi + off) = hi;
    *(__nv_bfloat16*)((char*)g_w1lo + off) = lo;
}

// ---------------- K1: h_pre_tilde ----------------
__global__ __launch_bounds__(128) void k1_hpt(const float* __restrict__ inp,
                                              const float* __restrict__ states){
    int b = blockIdx.x, n = threadIdx.x;
    __shared__ float corr[MS];
    if(n < MS) corr[n] = inp[(size_t)b*INC + NU + n];
    __syncthreads();
    const float* hp = states + (size_t)b*MS*NU;
    float a0=0.f,a1=0.f,a2=0.f,a3=0.f;
    #pragma unroll
    for(int m=0; m<MS; m+=4){
        a0 = fmaf(corr[m+0], hp[(m+0)*NU + n], a0);
        a1 = fmaf(corr[m+1], hp[(m+1)*NU + n], a1);
        a2 = fmaf(corr[m+2], hp[(m+2)*NU + n], a2);
        a3 = fmaf(corr[m+3], hp[(m+3)*NU + n], a3);
    }
    g_hpt[b*NU + n] = (a0+a1)+(a2+a3);
}

// ================= register-tiled GEMM core =================
__device__ __forceinline__ void gemm_rt(const float (*A)[NU], const float* __restrict__ W,
                                        float (*Ws)[NU], int rg, int cg, float acc[4][4]){
    int t = threadIdx.x;
    #pragma unroll 1
    for(int kt=0; kt<4; kt++){
        __syncthreads();
        const float4* src = (const float4*)(W + kt*32*NU);
        float4* dst = (float4*)Ws;
        #pragma unroll
        for(int i=0;i<4;i++) dst[t + i*256] = src[t + i*256];
        __syncthreads();
        #pragma unroll
        for(int k=0; k<32; k+=4){
            float4 w0 = *(const float4*)&Ws[k+0][cg*4];
            float4 w1 = *(const float4*)&Ws[k+1][cg*4];
            float4 w2 = *(const float4*)&Ws[k+2][cg*4];
            float4 w3 = *(const float4*)&Ws[k+3][cg*4];
            #pragma unroll
            for(int i=0;i<4;i++){
                float4 a = *(const float4*)&A[rg*4+i][kt*32+k];
                acc[i][0]=fmaf(a.x,w0.x,fmaf(a.y,w1.x,fmaf(a.z,w2.x,fmaf(a.w,w3.x,acc[i][0]))));
                acc[i][1]=fmaf(a.x,w0.y,fmaf(a.y,w1.y,fmaf(a.z,w2.y,fmaf(a.w,w3.y,acc[i][1]))));
                acc[i][2]=fmaf(a.x,w0.z,fmaf(a.y,w1.z,fmaf(a.z,w2.z,fmaf(a.w,w3.z,acc[i][2]))));
                acc[i][3]=fmaf(a.x,w0.w,fmaf(a.y,w1.w,fmaf(a.z,w2.w,fmaf(a.w,w3.w,acc[i][3]))));
            }
        }
    }
}

// ---------------- K2a: slot 0=preds, 1..3=gates, 4=c ----------------
struct SM2A {
    float A0[TB][NU];
    float A1[TB][NU];
    float Ws[32][NU];
    float fact[TB][4];
};

__global__ __launch_bounds__(256) void k2a(const float* __restrict__ inp,
    const float* __restrict__ outW, const float* __restrict__ outb,
    const float* __restrict__ tgW,  const float* __restrict__ tgb,
    const float* __restrict__ agW,  const float* __restrict__ agb,
    const float* __restrict__ hgW,  const float* __restrict__ hgb,
    const float* __restrict__ g3W,  const float* __restrict__ g3b){

    extern __shared__ char smraw[];
    SM2A& S = *(SM2A*)smraw;
    int t = threadIdx.x, rg = t>>5, cg = t&31;
    int b0 = blockIdx.x*TB;
    int slot = blockIdx.y;

    for(int i=t; i<TB*NU; i+=256){
        int r = i>>7, c = i&127;
        S.A0[r][c] = g_hpt[(b0+r)*NU + c];
        S.A1[r][c] = (slot==0) ? inp[(size_t)(b0+r)*INC + NU + MS + c]
                               : inp[(size_t)(b0+r)*INC + c];
    }
    for(int i=t; i<TB*3; i+=256){ int r=i/3, g=i%3; S.fact[r][g] = inp[(size_t)(b0+r)*INC + 320 + g]; }

    float acc[4][4];
    #pragma unroll
    for(int i=0;i<4;i++){ acc[i][0]=acc[i][1]=acc[i][2]=acc[i][3]=0.f; }

    if(slot == 0){
        gemm_rt(S.A0, outW,         S.Ws, rg, cg, acc);
        gemm_rt(S.A1, outW + NU*NU, S.Ws, rg, cg, acc);
        float s[4];
        #pragma unroll
        for(int i=0;i<4;i++){
            s[i]=0.f;
            #pragma unroll
            for(int j=0;j<4;j++) s[i] += sigmoidf(acc[i][j] + outb[cg*4+j]);
        }
        #pragma unroll
        for(int off=16; off; off>>=1){
            #pragma unroll
            for(int i=0;i<4;i++) s[i] += __shfl_xor_sync(0xffffffffu, s[i], off);
        }
        if(cg==0){
            #pragma unroll
            for(int i=0;i<4;i++) g_preds[b0 + rg*4 + i] = s[i] * (1.f/NU);
        }
    } else if(slot <= 3){
        int g = slot - 1;
        const float* Wg = (g==0)? tgW : (g==1)? agW : hgW;
        const float* bg = (g==0)? tgb : (g==1)? agb : hgb;
        gemm_rt(S.A0, Wg,         S.Ws, rg, cg, acc);
        gemm_rt(S.A1, Wg + NU*NU, S.Ws, rg, cg, acc);
        #pragma unroll
        for(int i=0;i<4;i++){
            int b = b0 + rg*4 + i;
            float f = S.fact[rg*4+i][g];
            float gain = 0.3f + 0.7f*sigmoidf(10.f*(f - 0.3f));
            float4 o;
            o.x = sigmoidf((acc[i][0] + bg[cg*4+0]) * gain);
            o.y = sigmoidf((acc[i][1] + bg[cg*4+1]) * gain);
            o.z = sigmoidf((acc[i][2] + bg[cg*4+2]) * gain);
            o.w = sigmoidf((acc[i][3] + bg[cg*4+3]) * gain);
            *(float4*)&g_gain[(size_t)g*BMAX*NU + b*NU + cg*4] = o;
        }
    } else {
        gemm_rt(S.A1, g3W + NU*NU, S.Ws, rg, cg, acc);
        #pragma unroll
        for(int i=0;i<4;i++){
            int b = b0 + rg*4 + i;
            float f0=S.fact[rg*4+i][0], f1=S.fact[rg*4+i][1], f2=S.fact[rg*4+i][2];
            #pragma unroll
            for(int j=0;j<4;j++){
                int n = cg*4 + j;
                g_c[b*NU + n] = acc[i][j] + f0*g_ws[n] + f1*g_ws[NU+n] + f2*g_ws[2*NU+n] + g3b[n];
            }
        }
    }
}

// ---------------- K2b: fusion dot products ----------------
struct SM2B {
    float A[TB][NU];
    float Ws[32][NU];
};

__global__ __launch_bounds__(256) void k2b(const float* __restrict__ tw,
    const float* __restrict__ aw, const float* __restrict__ hw){
    extern __shared__ char smraw[];
    SM2B& S = *(SM2B*)smraw;
    int t = threadIdx.x, rg = t>>5, cg = t&31;
    int b0 = blockIdx.x*TB;
    int y = blockIdx.y;
    int r = y/3, g = y%3;
    const float* W = (g==0)? tw : (g==1)? aw : hw;

    for(int i=t; i<TB*NU; i+=256){
        int rr = i>>7, c = i&127;
        S.A[rr][c] = g_gain[(size_t)g*BMAX*NU + (b0+rr)*NU + c];
    }

    float acc[4][4];
    #pragma unroll
    for(int i=0;i<4;i++){ acc[i][0]=acc[i][1]=acc[i][2]=acc[i][3]=0.f; }
    gemm_rt(S.A, W + (size_t)r*129*NU, S.Ws, rg, cg, acc);

    const float* pad = W + ((size_t)r*129 + 128)*NU;
    float* dst = g_fdot + (size_t)y*BMAX*NU;
    #pragma unroll
    for(int i=0;i<4;i++){
        int b = b0 + rg*4 + i;
        float4 o;
        o.x = acc[i][0] + pad[cg*4+0];
        o.y = acc[i][1] + pad[cg*4+1];
        o.z = acc[i][2] + pad[cg*4+2];
        o.w = acc[i][3] + pad[cg*4+3];
        *(float4*)&dst[b*NU + cg*4] = o;
    }
}

// ---------------- K3c: combine -> learning_gain ----------------
__global__ __launch_bounds__(256) void k3c(const float* __restrict__ Wf,
                                           const float* __restrict__ bias, int B){
    int idx = blockIdx.x*256 + threadIdx.x;
    size_t e = (size_t)idx*4;
    if(e >= (size_t)B*NU) return;
    int n = (int)(e & 127);
    float wfs[4] = {__ldg(Wf), __ldg(Wf+1), __ldg(Wf+2), __ldg(Wf+3)};
    float4 bs = *(const float4*)&bias[n];
    float4 acc = make_float4(0.f,0.f,0.f,0.f);
    #pragma unroll
    for(int r=0; r<4; r++){
        float4 p0 = *(const float4*)&g_fdot[(size_t)(r*3+0)*BMAX*NU + e];
        float4 p1 = *(const float4*)&g_fdot[(size_t)(r*3+1)*BMAX*NU + e];
        float4 p2 = *(const float4*)&g_fdot[(size_t)(r*3+2)*BMAX*NU + e];
        acc.x = fmaf(wfs[r], p0.x*p1.x*p2.x, acc.x);
        acc.y = fmaf(wfs[r], p0.y*p1.y*p2.y, acc.y);
        acc.z = fmaf(wfs[r], p0.z*p1.z*p2.z, acc.z);
        acc.w = fmaf(wfs[r], p0.w*p1.w*p2.w, acc.w);
    }
    float4 o;
    o.x = fmaxf(acc.x + bs.x, 0.f);
    o.y = fmaxf(acc.y + bs.y, 0.f);
    o.z = fmaxf(acc.z + bs.z, 0.f);
    o.w = fmaxf(acc.w + bs.w, 0.f);
    *(float4*)&g_lg[e] = o;
}

// ---------------- K4 v2: mma.sync GEMM (A from global) + state update + h_tilde ----------------
// One CTA = 2 batches (M=128 rows), 256 threads / 8 warps. W hi/lo in smem only.
#define SM4_WHI 0
#define SM4_WLO 32768
#define SM4_HTW 65536                     // 8*128 floats
#define SM4_AUX (65536 + 4096)
#define SM4_TOTAL (SM4_AUX + 2560)

__global__ __launch_bounds__(256, 2)
void k4_main(const float* __restrict__ inp, const float* __restrict__ states,
             float* __restrict__ out, int B){
    extern __shared__ char sm[];
    float* htw    = (float*)(sm + SM4_HTW);
    float* corr_s = (float*)(sm + SM4_AUX);
    float* c_s    = (float*)(sm + SM4_AUX + 512);
    float* lg_s   = (float*)(sm + SM4_AUX + 1536);

    int t = threadIdx.x, w = t>>5, l = t&31;
    int g = l>>2, tt = l&3;
    int bb = blockIdx.x;                  // batches 2bb, 2bb+1
    size_t row0 = (size_t)bb*128;

    // stage W hi/lo
    {
        const uint4* shv = (const uint4*)g_w1hi;
        const uint4* slv = (const uint4*)g_w1lo;
        uint4* dh = (uint4*)(sm + SM4_WHI);
        uint4* dl = (uint4*)(sm + SM4_WLO);
        for(int i=t; i<2048; i+=256){ dh[i]=shv[i]; dl[i]=slv[i]; }
    }
    if(t < 128) corr_s[t] = inp[(size_t)(2*bb + (t>>6))*INC + NU + (t&63)];
    c_s[t]  = g_c [(size_t)2*bb*NU + t];
    lg_s[t] = g_lg[(size_t)2*bb*NU + t];

    int r0 = w*16;
    const float* a00 = states + (row0 + r0 + g    )*NU;
    const float* a01 = states + (row0 + r0 + g + 8)*NU;

    float acc[16][4];
    #pragma unroll
    for(int nt=0; nt<16; nt++){ acc[nt][0]=acc[nt][1]=acc[nt][2]=acc[nt][3]=0.f; }

    __syncthreads();

    // software-pipelined mainloop over K (8 chunks of 16)
    float2 av0[4], av1[4];
    {
        int c0 = tt*2;
        av0[0] = *(const float2*)(a00 + c0);
        av0[1] = *(const float2*)(a01 + c0);
        av0[2] = *(const float2*)(a00 + c0 + 8);
        av0[3] = *(const float2*)(a01 + c0 + 8);
    }
    #pragma unroll
    for(int kt=0; kt<8; kt++){
        if(kt < 7){
            int c0 = (kt+1)*16 + tt*2;
            av1[0] = *(const float2*)(a00 + c0);
            av1[1] = *(const float2*)(a01 + c0);
            av1[2] = *(const float2*)(a00 + c0 + 8);
            av1[3] = *(const float2*)(a01 + c0 + 8);
        }
        uint32_t ah[4], al[4];
        #pragma unroll
        for(int i=0;i<4;i++){
            float x = av0[i].x, y = av0[i].y;
            __nv_bfloat16 hx = __float2bfloat16(x), hy = __float2bfloat16(y);
            ah[i] = bfu(hx) | (bfu(hy)<<16);
            al[i] = bfu(__float2bfloat16(x - __bfloat162float(hx)))
                  | (bfu(__float2bfloat16(y - __bfloat162float(hy)))<<16);
        }
        int cb0 = kt*32 + tt*4, cb1 = cb0 + 16;
        #pragma unroll
        for(int nt=0; nt<16; nt++){
            uint32_t bh0 = *(const uint32_t*)(sm + SM4_WHI + swzA(nt*8+g, cb0));
            uint32_t bh1 = *(const uint32_t*)(sm + SM4_WHI + swzA(nt*8+g, cb1));
            uint32_t bl0 = *(const uint32_t*)(sm + SM4_WLO + swzA(nt*8+g, cb0));
            uint32_t bl1 = *(const uint32_t*)(sm + SM4_WLO + swzA(nt*8+g, cb1));
            MMA16816(acc[nt], ah, bh0, bh1);
            MMA16816(acc[nt], al, bh0, bh1);
            MMA16816(acc[nt], ah, bl0, bl1);
        }
        #pragma unroll
        for(int i=0;i<4;i++) av0[i] = av1[i];
    }

    // epilogue: forget gate + state update + h_tilde partials
    int m0 = r0 + g, m1 = r0 + g + 8;     // same batch (m0,m1 in same 64-block)
    int boff = (m0 >> 6) * NU;
    float cr0 = corr_s[m0], cr1 = corr_s[m1];
    float* h0 = out + (size_t)2*B + (row0 + m0)*NU;
    float* h1 = out + (size_t)2*B + (row0 + m1)*NU;

    #pragma unroll
    for(int nt=0; nt<16; nt++){
        int n0 = nt*8 + tt*2;
        float2 a0v = *(const float2*)(a00 + n0);
        float2 a1v = *(const float2*)(a01 + n0);
        float2 cc  = *(const float2*)(c_s  + boff + n0);
        float2 ll  = *(const float2*)(lg_s + boff + n0);
        float2 o0, o1;
        o0.x = a0v.x * sigmoidf(acc[nt][0] + cc.x) + cr0*ll.x;
        o0.y = a0v.y * sigmoidf(acc[nt][1] + cc.y) + cr0*ll.y;
        o1.x = a1v.x * sigmoidf(acc[nt][2] + cc.x) + cr1*ll.x;
        o1.y = a1v.y * sigmoidf(acc[nt][3] + cc.y) + cr1*ll.y;
        *(float2*)(h0 + n0) = o0;
        *(float2*)(h1 + n0) = o1;
        // h_tilde partial for cols n0, n0+1 from rows m0, m1
        float px = fmaf(cr0, o0.x, cr1*o1.x);
        float py = fmaf(cr0, o0.y, cr1*o1.y);
        // reduce over g (lane bits [4:2])
        px += __shfl_xor_sync(0xffffffffu, px, 4);
        py += __shfl_xor_sync(0xffffffffu, py, 4);
        px += __shfl_xor_sync(0xffffffffu, px, 8);
        py += __shfl_xor_sync(0xffffffffu, py, 8);
        px += __shfl_xor_sync(0xffffffffu, px, 16);
        py += __shfl_xor_sync(0xffffffffu, py, 16);
        if(g == 0){ htw[w*NU + n0] = px; htw[w*NU + n0 + 1] = py; }
    }
    __syncthreads();
    {
        int batch = t>>7, col = t&127;
        float s = htw[(batch*4+0)*NU + col] + htw[(batch*4+1)*NU + col]
                + htw[(batch*4+2)*NU + col] + htw[(batch*4+3)*NU + col];
        g_htilde[(size_t)(2*bb + batch)*NU + col] = s;
    }
}

// ---------------- K5 v2: after_preds from g_htilde + result ----------------
struct SM5 {
    float A0[TB][NU];
    float A1[TB][NU];
    float Ws[32][NU];
};

__global__ __launch_bounds__(256) void k5_out(const float* __restrict__ inp,
                                              const float* __restrict__ outW,
                                              const float* __restrict__ outb,
                                              float* __restrict__ out, int B){
    extern __shared__ char smraw[];
    SM5& S = *(SM5*)smraw;
    int t = threadIdx.x, rg = t>>5, cg = t&31;
    int b0 = blockIdx.x*TB;

    for(int i=t; i<TB*NU; i+=256){
        int r = i>>7, c = i&127;
        S.A0[r][c] = g_htilde[(size_t)(b0+r)*NU + c];
        S.A1[r][c] = inp[(size_t)(b0+r)*INC + NU + MS + c];
    }

    float acc[4][4];
    #pragma unroll
    for(int i=0;i<4;i++){ acc[i][0]=acc[i][1]=acc[i][2]=acc[i][3]=0.f; }
    gemm_rt(S.A0, outW,         S.Ws, rg, cg, acc);
    gemm_rt(S.A1, outW + NU*NU, S.Ws, rg, cg, acc);

    float s[4];
    #pragma unroll
    for(int i=0;i<4;i++){
        s[i]=0.f;
        #pragma unroll
        for(int j=0;j<4;j++) s[i] += sigmoidf(acc[i][j] + outb[cg*4+j]);
    }
    #pragma unroll
    for(int off=16; off; off>>=1){
        #pragma unroll
        for(int i=0;i<4;i++) s[i] += __shfl_xor_sync(0xffffffffu, s[i], off);
    }
    if(cg==0){
        #pragma unroll
        for(int i=0;i<4;i++){
            int b = b0 + rg*4 + i;
            float p  = g_preds[b];
            float ap = s[i] * (1.f/NU);
            out[(size_t)b*2]     = p;
            out[(size_t)b*2 + 1] = (ap - p) / (1.f - p);
        }
    }
}

// ---------------- launch ----------------
extern "C" void kernel_launch(void* const* d_in, const int* in_sizes, int n_in,
                              void* d_out, int out_size){
    const float* inp    = (const float*)d_in[0];
    const float* states = (const float*)d_in[1];
    const float* tw     = (const float*)d_in[2];
    const float* aw     = (const float*)d_in[3];
    const float* hw     = (const float*)d_in[4];
    const float* Wf     = (const float*)d_in[5];
    const float* bias   = (const float*)d_in[6];
    const float* g3W    = (const float*)d_in[7];
    const float* g3b    = (const float*)d_in[8];
    const float* outW   = (const float*)d_in[9];
    const float* outb   = (const float*)d_in[10];
    const float* tgW    = (const float*)d_in[11];
    const float* tgb    = (const float*)d_in[12];
    const float* agW    = (const float*)d_in[13];
    const float* agb    = (const float*)d_in[14];
    const float* hgW    = (const float*)d_in[15];
    const float* hgb    = (const float*)d_in[16];
    float* out = (float*)d_out;
    int B = in_sizes[0] / INC;

    cudaFuncSetAttribute(k2a,     cudaFuncAttributeMaxDynamicSharedMemorySize, (int)sizeof(SM2A));
    cudaFuncSetAttribute(k2b,     cudaFuncAttributeMaxDynamicSharedMemorySize, (int)sizeof(SM2B));
    cudaFuncSetAttribute(k4_main, cudaFuncAttributeMaxDynamicSharedMemorySize, SM4_TOTAL);
    cudaFuncSetAttribute(k5_out,  cudaFuncAttributeMaxDynamicSharedMemorySize, (int)sizeof(SM5));

    k0_wsum   <<<1, 128>>>(g3W);
    k0b_wsplit<<<64, 256>>>(g3W);
    k1_hpt    <<<B, 128>>>(inp, states);
    {
        dim3 g2a(B/TB, 5);
        k2a<<<g2a, 256, sizeof(SM2A)>>>(inp, outW, outb, tgW, tgb, agW, agb, hgW, hgb, g3W, g3b);
    }
    {
        dim3 g2b(B/TB, 12);
        k2b<<<g2b, 256, sizeof(SM2B)>>>(tw, aw, hw);
    }
    k3c      <<<(B*NU/4 + 255)/256, 256>>>(Wf, bias, B);
    k4_main  <<<B/2, 256, SM4_TOTAL>>>(inp, states, out, B);
    k5_out   <<<B/TB, 256, sizeof(SM5)>>>(inp, outW, outb, out, B);
}